// round 2
// baseline (speedup 1.0000x reference)
#include <cuda_runtime.h>
#include <math.h>

// Problem constants
#define BSZ   4
#define LSEQ  2048
#define DMOD  1024
#define NHEAD 16
#define HDIM  64
#define MROWS (BSZ * LSEQ)      // 8192
#define NQKV  (3 * DMOD)        // 3072

// Scratch (allocation-free rule: device globals)
__device__ float g_qkv[(size_t)MROWS * NQKV];   // [B*L, 3D]
__device__ float g_y[(size_t)MROWS * DMOD];     // attention output [B*L, D]

// ---------------------------------------------------------------------------
// SGEMM + bias: C[M,N] = A[M,K] @ W[K,N] + bias[N]
// 128x128 block tile, BK=16, 256 threads, 8x8 per-thread register tile.
// M % 128 == 0, N % 128 == 0, K % 16 == 0 guaranteed by problem shapes.
// ---------------------------------------------------------------------------
__global__ __launch_bounds__(256, 2)
void sgemm_bias_kernel(const float* __restrict__ A,
                       const float* __restrict__ W,
                       const float* __restrict__ bias,
                       float* __restrict__ C,
                       int M, int N, int K)
{
    constexpr int BM = 128, BN = 128, BK = 16;
    __shared__ __align__(16) float As[BK][BM];   // A transposed: As[k][m]
    __shared__ __align__(16) float Bs[BK][BN];

    const int tid = threadIdx.x;
    const int ty  = tid >> 4;       // 0..15
    const int tx  = tid & 15;       // 0..15
    const int m0  = blockIdx.y * BM;
    const int n0  = blockIdx.x * BN;

    float acc[8][8];
    #pragma unroll
    for (int i = 0; i < 8; i++)
        #pragma unroll
        for (int j = 0; j < 8; j++)
            acc[i][j] = 0.0f;

    for (int k0 = 0; k0 < K; k0 += BK) {
        // Load A tile (128 x 16) as float4 along K, store transposed.
        #pragma unroll
        for (int it = 0; it < 2; it++) {
            int slot = tid + it * 256;          // 0..511
            int row  = slot >> 2;               // 0..127
            int kc   = (slot & 3) << 2;         // 0,4,8,12
            float4 v = *(const float4*)&A[(size_t)(m0 + row) * K + k0 + kc];
            As[kc + 0][row] = v.x;
            As[kc + 1][row] = v.y;
            As[kc + 2][row] = v.z;
            As[kc + 3][row] = v.w;
        }
        // Load B tile (16 x 128) as float4 along N.
        #pragma unroll
        for (int it = 0; it < 2; it++) {
            int slot = tid + it * 256;          // 0..511
            int row  = slot >> 5;               // 0..15
            int col  = (slot & 31) << 2;        // 0..124
            *(float4*)&Bs[row][col] =
                *(const float4*)&W[(size_t)(k0 + row) * N + n0 + col];
        }
        __syncthreads();

        #pragma unroll
        for (int k = 0; k < BK; k++) {
            float a[8], b[8];
            *(float4*)&a[0] = *(float4*)&As[k][ty * 8];
            *(float4*)&a[4] = *(float4*)&As[k][ty * 8 + 4];
            *(float4*)&b[0] = *(float4*)&Bs[k][tx * 8];
            *(float4*)&b[4] = *(float4*)&Bs[k][tx * 8 + 4];
            #pragma unroll
            for (int i = 0; i < 8; i++)
                #pragma unroll
                for (int j = 0; j < 8; j++)
                    acc[i][j] = fmaf(a[i], b[j], acc[i][j]);
        }
        __syncthreads();
    }

    // Epilogue with bias, float4 stores. Bias loads hoisted (invariant in i).
    float4 bv0 = *(const float4*)&bias[n0 + tx * 8];
    float4 bv1 = *(const float4*)&bias[n0 + tx * 8 + 4];
    #pragma unroll
    for (int i = 0; i < 8; i++) {
        int m = m0 + ty * 8 + i;
        float4 o0, o1;
        o0.x = acc[i][0] + bv0.x;  o0.y = acc[i][1] + bv0.y;
        o0.z = acc[i][2] + bv0.z;  o0.w = acc[i][3] + bv0.w;
        o1.x = acc[i][4] + bv1.x;  o1.y = acc[i][5] + bv1.y;
        o1.z = acc[i][6] + bv1.z;  o1.w = acc[i][7] + bv1.w;
        *(float4*)&C[(size_t)m * N + n0 + tx * 8]     = o0;
        *(float4*)&C[(size_t)m * N + n0 + tx * 8 + 4] = o1;
    }
}

// ---------------------------------------------------------------------------
// Flash-attention (causal), fp32. One block = one (b, h, q-tile of 64).
// 256 threads, 4x4 register tile over the 64x64 S / O tiles.
// Smem: Qt (transposed+swizzled), KPt (K transposed, reused for P^T), Vs.
// Exactly 48 KB static smem.
// ---------------------------------------------------------------------------
__device__ __forceinline__ float hmax16(float v) {
    #pragma unroll
    for (int off = 8; off > 0; off >>= 1)
        v = fmaxf(v, __shfl_xor_sync(0xffffffffu, v, off));
    return v;
}
__device__ __forceinline__ float hsum16(float v) {
    #pragma unroll
    for (int off = 8; off > 0; off >>= 1)
        v += __shfl_xor_sync(0xffffffffu, v, off);
    return v;
}

__global__ __launch_bounds__(256, 2)
void attn_kernel(const float* __restrict__ qkv, float* __restrict__ y)
{
    // [d][i] transposed layouts with XOR swizzle at float4 granularity:
    // phys(d, i) = d*64 + 4*((i>>2) ^ (d & 15)) + (i & 3)
    __shared__ __align__(16) float Qt[64 * 64];
    __shared__ __align__(16) float KPt[64 * 64];   // K^T, later P^T
    __shared__ __align__(16) float Vs[64 * 64];    // natural [j][d]

    const int tid = threadIdx.x;
    const int ty  = tid >> 4;      // 0..15 -> rows i = 4*ty..
    const int tx  = tid & 15;      // 0..15 -> cols j/d = 4*tx..
    const int qt  = gridDim.x - 1 - blockIdx.x;   // long rows first
    const int bh  = blockIdx.y;
    const int b   = bh >> 4;
    const int h   = bh & 15;
    const int q0  = qt * 64;

    const float* base = qkv + (size_t)(b * LSEQ) * NQKV + h * HDIM;

    // Load Q tile transposed+swizzled.
    #pragma unroll
    for (int it = 0; it < 4; it++) {
        int slot = tid + it * 256;      // 0..1023
        int r    = slot >> 4;           // query row in tile 0..63
        int d4   = slot & 15;           // float4 index along HDIM
        float4 v = *(const float4*)&base[(size_t)(q0 + r) * NQKV + d4 * 4];
        int i4 = r >> 2, ir = r & 3;
        float vv[4] = {v.x, v.y, v.z, v.w};
        #pragma unroll
        for (int c = 0; c < 4; c++) {
            int d = d4 * 4 + c;
            Qt[d * 64 + ((i4 ^ (d & 15)) << 2) + ir] = vv[c];
        }
    }

    float o[4][4];
    float m_i[4], l_i[4];
    #pragma unroll
    for (int r = 0; r < 4; r++) {
        m_i[r] = -1e30f;
        l_i[r] = 0.0f;
        #pragma unroll
        for (int c = 0; c < 4; c++) o[r][c] = 0.0f;
    }

    for (int kt = 0; kt <= qt; kt++) {
        const int k0 = kt * 64;
        // Load K (transposed+swizzled) and V (natural).
        #pragma unroll
        for (int it = 0; it < 4; it++) {
            int slot = tid + it * 256;
            int r    = slot >> 4;
            int d4   = slot & 15;
            const float* krow = base + DMOD + (size_t)(k0 + r) * NQKV;
            const float* vrow = base + 2 * DMOD + (size_t)(k0 + r) * NQKV;
            float4 kv = *(const float4*)&krow[d4 * 4];
            *(float4*)&Vs[r * 64 + d4 * 4] = *(const float4*)&vrow[d4 * 4];
            int i4 = r >> 2, ir = r & 3;
            float kk[4] = {kv.x, kv.y, kv.z, kv.w};
            #pragma unroll
            for (int c = 0; c < 4; c++) {
                int d = d4 * 4 + c;
                KPt[d * 64 + ((i4 ^ (d & 15)) << 2) + ir] = kk[c];
            }
        }
        __syncthreads();

        // S = Q @ K^T (4x4 per thread)
        float s[4][4];
        #pragma unroll
        for (int r = 0; r < 4; r++)
            #pragma unroll
            for (int c = 0; c < 4; c++) s[r][c] = 0.0f;

        #pragma unroll 8
        for (int d = 0; d < 64; d++) {
            float4 qv = *(float4*)&Qt[d * 64 + ((ty ^ (d & 15)) << 2)];
            float4 kv = *(float4*)&KPt[d * 64 + ((tx ^ (d & 15)) << 2)];
            float qa[4] = {qv.x, qv.y, qv.z, qv.w};
            float ka[4] = {kv.x, kv.y, kv.z, kv.w};
            #pragma unroll
            for (int r = 0; r < 4; r++)
                #pragma unroll
                for (int c = 0; c < 4; c++)
                    s[r][c] = fmaf(qa[r], ka[c], s[r][c]);
        }

        // Scale + causal mask (only diagonal tile needs masking).
        const float scale = 0.125f;   // 1/sqrt(64)
        if (kt == qt) {
            #pragma unroll
            for (int r = 0; r < 4; r++)
                #pragma unroll
                for (int c = 0; c < 4; c++) {
                    float sv = s[r][c] * scale;
                    if (k0 + tx * 4 + c > q0 + ty * 4 + r) sv = -1e30f;
                    s[r][c] = sv;
                }
        } else {
            #pragma unroll
            for (int r = 0; r < 4; r++)
                #pragma unroll
                for (int c = 0; c < 4; c++) s[r][c] *= scale;
        }

        // Online softmax update.
        float alpha[4], rs[4];
        #pragma unroll
        for (int r = 0; r < 4; r++) {
            float mrow = fmaxf(fmaxf(s[r][0], s[r][1]), fmaxf(s[r][2], s[r][3]));
            mrow = hmax16(mrow);
            float mn = fmaxf(m_i[r], mrow);
            alpha[r] = __expf(m_i[r] - mn);
            m_i[r] = mn;
            float acc = 0.0f;
            #pragma unroll
            for (int c = 0; c < 4; c++) {
                float p = __expf(s[r][c] - mn);
                s[r][c] = p;
                acc += p;
            }
            rs[r] = hsum16(acc);
        }
        #pragma unroll
        for (int r = 0; r < 4; r++) {
            l_i[r] = l_i[r] * alpha[r] + rs[r];
            #pragma unroll
            for (int c = 0; c < 4; c++) o[r][c] *= alpha[r];
        }

        __syncthreads();   // everyone done reading KPt as K

        // Write P^T (swizzled) into KPt: Pt[j][i] = p[i][j]
        #pragma unroll
        for (int c = 0; c < 4; c++) {
            int j = tx * 4 + c;
            #pragma unroll
            for (int r = 0; r < 4; r++) {
                int i = ty * 4 + r;
                KPt[j * 64 + (((i >> 2) ^ (j & 15)) << 2) + (i & 3)] = s[r][c];
            }
        }
        __syncthreads();

        // O += P @ V : o[i][d] += sum_j Pt[j][i] * Vs[j][d]
        #pragma unroll 8
        for (int j = 0; j < 64; j++) {
            float4 pv = *(float4*)&KPt[j * 64 + ((ty ^ (j & 15)) << 2)];
            float4 vv = *(float4*)&Vs[j * 64 + tx * 4];
            float pa[4] = {pv.x, pv.y, pv.z, pv.w};
            float va[4] = {vv.x, vv.y, vv.z, vv.w};
            #pragma unroll
            for (int r = 0; r < 4; r++)
                #pragma unroll
                for (int c = 0; c < 4; c++)
                    o[r][c] = fmaf(pa[r], va[c], o[r][c]);
        }
        __syncthreads();   // before next tile overwrites KPt / Vs
    }

    // Epilogue: normalize, write y[b*L + q, h*HD + d]
    #pragma unroll
    for (int r = 0; r < 4; r++) {
        float inv = 1.0f / l_i[r];
        float4 ov;
        ov.x = o[r][0] * inv;
        ov.y = o[r][1] * inv;
        ov.z = o[r][2] * inv;
        ov.w = o[r][3] * inv;
        size_t row = (size_t)(b * LSEQ + q0 + ty * 4 + r);
        *(float4*)&y[row * DMOD + h * HDIM + tx * 4] = ov;
    }
}

// ---------------------------------------------------------------------------
// Launch
// ---------------------------------------------------------------------------
extern "C" void kernel_launch(void* const* d_in, const int* in_sizes, int n_in,
                              void* d_out, int out_size)
{
    (void)in_sizes; (void)n_in; (void)out_size;
    const float* x     = (const float*)d_in[0];
    const float* Wqkv  = (const float*)d_in[1];
    const float* bqkv  = (const float*)d_in[2];
    const float* Wproj = (const float*)d_in[3];
    const float* bproj = (const float*)d_in[4];
    float* out = (float*)d_out;

    float* qkvp = nullptr;
    float* yp   = nullptr;
    cudaGetSymbolAddress((void**)&qkvp, g_qkv);
    cudaGetSymbolAddress((void**)&yp, g_y);

    dim3 blk(256);
    // QKV projection: [8192,1024] @ [1024,3072] + b
    sgemm_bias_kernel<<<dim3(NQKV / 128, MROWS / 128), blk>>>(
        x, Wqkv, bqkv, qkvp, MROWS, NQKV, DMOD);
    // Causal flash attention
    attn_kernel<<<dim3(LSEQ / 64, BSZ * NHEAD), blk>>>(qkvp, yp);
    // Output projection: [8192,1024] @ [1024,1024] + b
    sgemm_bias_kernel<<<dim3(DMOD / 128, MROWS / 128), blk>>>(
        yp, Wproj, bproj, out, MROWS, DMOD, DMOD);
}

// round 5
// speedup vs baseline: 1.5358x; 1.5358x over previous
#include <cuda_runtime.h>
#include <math.h>
#include <stdint.h>

// Problem constants
#define BSZ   4
#define LSEQ  2048
#define DMOD  1024
#define NHEAD 16
#define HDIM  64
#define MROWS (BSZ * LSEQ)      // 8192
#define NQKV  (3 * DMOD)        // 3072

// Scratch (allocation-free rule: device globals)
__device__ float g_qkv[(size_t)MROWS * NQKV];   // [B*L, 3D]
__device__ float g_y[(size_t)MROWS * DMOD];     // attention output [B*L, D]

// ===========================================================================
// Helpers: cp.async + tf32 mma.sync (all plain-sm_100-legal, sm_80+ features)
// ===========================================================================
__device__ __forceinline__ uint32_t smem_u32(const void* p) {
    uint32_t a;
    asm("{ .reg .u64 t; cvta.to.shared.u64 t, %1; cvt.u32.u64 %0, t; }"
        : "=r"(a) : "l"(p));
    return a;
}
__device__ __forceinline__ void cp_async16(uint32_t dst, const void* src) {
    asm volatile("cp.async.cg.shared.global [%0], [%1], 16;"
                 :: "r"(dst), "l"(src) : "memory");
}
__device__ __forceinline__ void cp_commit() {
    asm volatile("cp.async.commit_group;" ::: "memory");
}
#define CP_WAIT(n) asm volatile("cp.async.wait_group %0;" :: "n"(n) : "memory")

__device__ __forceinline__ uint32_t f2tf32(float f) {
    uint32_t r;
    asm("cvt.rna.tf32.f32 %0, %1;" : "=r"(r) : "f"(f));
    return r;
}
__device__ __forceinline__ void mma_tf32(float* c, const uint32_t* a, const uint32_t* b) {
    asm volatile(
        "mma.sync.aligned.m16n8k8.row.col.f32.tf32.tf32.f32 "
        "{%0,%1,%2,%3}, {%4,%5,%6,%7}, {%8,%9}, {%0,%1,%2,%3};\n"
        : "+f"(c[0]), "+f"(c[1]), "+f"(c[2]), "+f"(c[3])
        : "r"(a[0]), "r"(a[1]), "r"(a[2]), "r"(a[3]), "r"(b[0]), "r"(b[1]));
}

// ===========================================================================
// tf32 tensor-core GEMM + bias: C[M,N] = A[M,K] @ W[K,N] + bias[N]
// CTA 128x128, BK=16, 4-stage cp.async pipeline, 256 threads.
// Warp grid 2(m) x 4(n): warp tile 64x32 -> 4x4 m16n8k8 tiles per k-step.
// A smem: [m][k] rows padded to 20 floats (80B)   -> conflict-free frag loads
// B smem: [k][n] rows padded to 136 floats (544B) -> conflict-free frag loads
// ===========================================================================
#define GSTAGES 4
#define GBK 16
#define A_ST_F (128 * 20)         // floats per A stage (10240 B)
#define B_ST_F (16 * 136)         // floats per B stage (8704 B)
#define ST_F   (A_ST_F + B_ST_F)  // 4736 floats = 18944 B
#define GEMM_SMEM (GSTAGES * ST_F * 4)   // 75776 B

__global__ __launch_bounds__(256, 1)
void gemm_tc(const float* __restrict__ A, const float* __restrict__ W,
             const float* __restrict__ bias, float* __restrict__ C,
             int M, int N, int K)
{
    extern __shared__ __align__(16) float sm_f[];
    const uint32_t sm_b = smem_u32(sm_f);

    const int tid  = threadIdx.x;
    const int wid  = tid >> 5;
    const int lane = tid & 31;
    const int grp  = lane >> 2;      // 0..7
    const int qid  = lane & 3;       // 0..3
    const int wm   = wid >> 2;       // 0..1
    const int wn   = wid & 3;        // 0..3
    const int m0   = blockIdx.y * 128;
    const int n0   = blockIdx.x * 128;
    const int NCHUNK = K / GBK;

    float acc[4][4][4];
    #pragma unroll
    for (int mi = 0; mi < 4; mi++)
        #pragma unroll
        for (int ni = 0; ni < 4; ni++)
            #pragma unroll
            for (int q = 0; q < 4; q++) acc[mi][ni][q] = 0.0f;

    // -------- stage loader (all 256 threads; 2+2 cp.async16 each) --------
    auto load_stage = [&](int s, int k0) {
        const uint32_t as = sm_b + s * (ST_F * 4);
        const uint32_t bs = as + A_ST_F * 4;
        #pragma unroll
        for (int i = 0; i < 2; i++) {
            int id  = tid + i * 256;       // 0..511
            int row = id >> 2;             // 0..127
            int ch  = id & 3;              // 16B chunk in 64B row
            cp_async16(as + row * 80 + ch * 16,
                       A + (size_t)(m0 + row) * K + k0 + ch * 4);
        }
        #pragma unroll
        for (int i = 0; i < 2; i++) {
            int id  = tid + i * 256;       // 0..511
            int row = id >> 5;             // 0..15
            int ch  = id & 31;             // 16B chunk in 512B row
            cp_async16(bs + row * 544 + ch * 16,
                       W + (size_t)(k0 + row) * N + n0 + ch * 4);
        }
        cp_commit();
    };

    // Prologue: fill STAGES-1 stages
    #pragma unroll
    for (int s = 0; s < GSTAGES - 1; s++) load_stage(s, s * GBK);

    for (int c = 0; c < NCHUNK; c++) {
        CP_WAIT(GSTAGES - 2);
        __syncthreads();
        {
            int nc = c + GSTAGES - 1;
            if (nc < NCHUNK) load_stage(nc % GSTAGES, nc * GBK);
        }

        const float* as = sm_f + (c % GSTAGES) * ST_F;
        const float* bs = as + A_ST_F;

        #pragma unroll
        for (int ks = 0; ks < 2; ks++) {
            const int kc = ks * 8;
            uint32_t af[4][4], bf[4][2];
            #pragma unroll
            for (int mi = 0; mi < 4; mi++) {
                int r = wm * 64 + mi * 16 + grp;
                int cc = kc + qid;
                af[mi][0] = f2tf32(as[r * 20 + cc]);
                af[mi][1] = f2tf32(as[(r + 8) * 20 + cc]);
                af[mi][2] = f2tf32(as[r * 20 + cc + 4]);
                af[mi][3] = f2tf32(as[(r + 8) * 20 + cc + 4]);
            }
            #pragma unroll
            for (int ni = 0; ni < 4; ni++) {
                int n = wn * 32 + ni * 8 + grp;
                int kk = kc + qid;
                bf[ni][0] = f2tf32(bs[kk * 136 + n]);
                bf[ni][1] = f2tf32(bs[(kk + 4) * 136 + n]);
            }
            #pragma unroll
            for (int mi = 0; mi < 4; mi++)
                #pragma unroll
                for (int ni = 0; ni < 4; ni++)
                    mma_tf32(acc[mi][ni], af[mi], bf[ni]);
        }
        __syncthreads();
    }

    // -------- epilogue: bias + float2 stores --------
    #pragma unroll
    for (int mi = 0; mi < 4; mi++) {
        int r0 = m0 + wm * 64 + mi * 16 + grp;
        #pragma unroll
        for (int ni = 0; ni < 4; ni++) {
            int col = n0 + wn * 32 + ni * 8 + qid * 2;
            float2 bv = *(const float2*)&bias[col];
            float2 o0, o1;
            o0.x = acc[mi][ni][0] + bv.x;  o0.y = acc[mi][ni][1] + bv.y;
            o1.x = acc[mi][ni][2] + bv.x;  o1.y = acc[mi][ni][3] + bv.y;
            *(float2*)&C[(size_t)r0 * N + col]       = o0;
            *(float2*)&C[(size_t)(r0 + 8) * N + col] = o1;
        }
    }
}

// ===========================================================================
// Flash-attention (causal), fp32 (unchanged round-2 baseline; mma port next)
// ===========================================================================
__device__ __forceinline__ float hmax16(float v) {
    #pragma unroll
    for (int off = 8; off > 0; off >>= 1)
        v = fmaxf(v, __shfl_xor_sync(0xffffffffu, v, off));
    return v;
}
__device__ __forceinline__ float hsum16(float v) {
    #pragma unroll
    for (int off = 8; off > 0; off >>= 1)
        v += __shfl_xor_sync(0xffffffffu, v, off);
    return v;
}

__global__ __launch_bounds__(256, 2)
void attn_kernel(const float* __restrict__ qkv, float* __restrict__ y)
{
    __shared__ __align__(16) float Qt[64 * 64];
    __shared__ __align__(16) float KPt[64 * 64];
    __shared__ __align__(16) float Vs[64 * 64];

    const int tid = threadIdx.x;
    const int ty  = tid >> 4;
    const int tx  = tid & 15;
    const int qt  = gridDim.x - 1 - blockIdx.x;
    const int bh  = blockIdx.y;
    const int b   = bh >> 4;
    const int h   = bh & 15;
    const int q0  = qt * 64;

    const float* base = qkv + (size_t)(b * LSEQ) * NQKV + h * HDIM;

    #pragma unroll
    for (int it = 0; it < 4; it++) {
        int slot = tid + it * 256;
        int r    = slot >> 4;
        int d4   = slot & 15;
        float4 v = *(const float4*)&base[(size_t)(q0 + r) * NQKV + d4 * 4];
        int i4 = r >> 2, ir = r & 3;
        float vv[4] = {v.x, v.y, v.z, v.w};
        #pragma unroll
        for (int c = 0; c < 4; c++) {
            int d = d4 * 4 + c;
            Qt[d * 64 + ((i4 ^ (d & 15)) << 2) + ir] = vv[c];
        }
    }

    float o[4][4];
    float m_i[4], l_i[4];
    #pragma unroll
    for (int r = 0; r < 4; r++) {
        m_i[r] = -1e30f;
        l_i[r] = 0.0f;
        #pragma unroll
        for (int c = 0; c < 4; c++) o[r][c] = 0.0f;
    }

    for (int kt = 0; kt <= qt; kt++) {
        const int k0 = kt * 64;
        #pragma unroll
        for (int it = 0; it < 4; it++) {
            int slot = tid + it * 256;
            int r    = slot >> 4;
            int d4   = slot & 15;
            const float* krow = base + DMOD + (size_t)(k0 + r) * NQKV;
            const float* vrow = base + 2 * DMOD + (size_t)(k0 + r) * NQKV;
            float4 kv = *(const float4*)&krow[d4 * 4];
            *(float4*)&Vs[r * 64 + d4 * 4] = *(const float4*)&vrow[d4 * 4];
            int i4 = r >> 2, ir = r & 3;
            float kk[4] = {kv.x, kv.y, kv.z, kv.w};
            #pragma unroll
            for (int c = 0; c < 4; c++) {
                int d = d4 * 4 + c;
                KPt[d * 64 + ((i4 ^ (d & 15)) << 2) + ir] = kk[c];
            }
        }
        __syncthreads();

        float s[4][4];
        #pragma unroll
        for (int r = 0; r < 4; r++)
            #pragma unroll
            for (int c = 0; c < 4; c++) s[r][c] = 0.0f;

        #pragma unroll 8
        for (int d = 0; d < 64; d++) {
            float4 qv = *(float4*)&Qt[d * 64 + ((ty ^ (d & 15)) << 2)];
            float4 kv = *(float4*)&KPt[d * 64 + ((tx ^ (d & 15)) << 2)];
            float qa[4] = {qv.x, qv.y, qv.z, qv.w};
            float ka[4] = {kv.x, kv.y, kv.z, kv.w};
            #pragma unroll
            for (int r = 0; r < 4; r++)
                #pragma unroll
                for (int c = 0; c < 4; c++)
                    s[r][c] = fmaf(qa[r], ka[c], s[r][c]);
        }

        const float scale = 0.125f;
        if (kt == qt) {
            #pragma unroll
            for (int r = 0; r < 4; r++)
                #pragma unroll
                for (int c = 0; c < 4; c++) {
                    float sv = s[r][c] * scale;
                    if (k0 + tx * 4 + c > q0 + ty * 4 + r) sv = -1e30f;
                    s[r][c] = sv;
                }
        } else {
            #pragma unroll
            for (int r = 0; r < 4; r++)
                #pragma unroll
                for (int c = 0; c < 4; c++) s[r][c] *= scale;
        }

        float alpha[4], rs[4];
        #pragma unroll
        for (int r = 0; r < 4; r++) {
            float mrow = fmaxf(fmaxf(s[r][0], s[r][1]), fmaxf(s[r][2], s[r][3]));
            mrow = hmax16(mrow);
            float mn = fmaxf(m_i[r], mrow);
            alpha[r] = __expf(m_i[r] - mn);
            m_i[r] = mn;
            float a2 = 0.0f;
            #pragma unroll
            for (int c = 0; c < 4; c++) {
                float p = __expf(s[r][c] - mn);
                s[r][c] = p;
                a2 += p;
            }
            rs[r] = hsum16(a2);
        }
        #pragma unroll
        for (int r = 0; r < 4; r++) {
            l_i[r] = l_i[r] * alpha[r] + rs[r];
            #pragma unroll
            for (int c = 0; c < 4; c++) o[r][c] *= alpha[r];
        }

        __syncthreads();

        #pragma unroll
        for (int c = 0; c < 4; c++) {
            int j = tx * 4 + c;
            #pragma unroll
            for (int r = 0; r < 4; r++) {
                int i = ty * 4 + r;
                KPt[j * 64 + (((i >> 2) ^ (j & 15)) << 2) + (i & 3)] = s[r][c];
            }
        }
        __syncthreads();

        #pragma unroll 8
        for (int j = 0; j < 64; j++) {
            float4 pv = *(float4*)&KPt[j * 64 + ((ty ^ (j & 15)) << 2)];
            float4 vv = *(float4*)&Vs[j * 64 + tx * 4];
            float pa[4] = {pv.x, pv.y, pv.z, pv.w};
            float va[4] = {vv.x, vv.y, vv.z, vv.w};
            #pragma unroll
            for (int r = 0; r < 4; r++)
                #pragma unroll
                for (int c = 0; c < 4; c++)
                    o[r][c] = fmaf(pa[r], va[c], o[r][c]);
        }
        __syncthreads();
    }

    #pragma unroll
    for (int r = 0; r < 4; r++) {
        float inv = 1.0f / l_i[r];
        float4 ov;
        ov.x = o[r][0] * inv;
        ov.y = o[r][1] * inv;
        ov.z = o[r][2] * inv;
        ov.w = o[r][3] * inv;
        size_t row = (size_t)(b * LSEQ + q0 + ty * 4 + r);
        *(float4*)&y[row * DMOD + h * HDIM + tx * 4] = ov;
    }
}

// ===========================================================================
// Launch
// ===========================================================================
extern "C" void kernel_launch(void* const* d_in, const int* in_sizes, int n_in,
                              void* d_out, int out_size)
{
    (void)in_sizes; (void)n_in; (void)out_size;
    const float* x     = (const float*)d_in[0];
    const float* Wqkv  = (const float*)d_in[1];
    const float* bqkv  = (const float*)d_in[2];
    const float* Wproj = (const float*)d_in[3];
    const float* bproj = (const float*)d_in[4];
    float* out = (float*)d_out;

    float* qkvp = nullptr;
    float* yp   = nullptr;
    cudaGetSymbolAddress((void**)&qkvp, g_qkv);
    cudaGetSymbolAddress((void**)&yp, g_y);

    static bool attr_set = false;
    if (!attr_set) {
        cudaFuncSetAttribute(gemm_tc, cudaFuncAttributeMaxDynamicSharedMemorySize,
                             GEMM_SMEM);
        attr_set = true;
    }

    // QKV projection: [8192,1024] @ [1024,3072] + b
    gemm_tc<<<dim3(NQKV / 128, MROWS / 128), 256, GEMM_SMEM>>>(
        x, Wqkv, bqkv, qkvp, MROWS, NQKV, DMOD);
    // Causal flash attention
    attn_kernel<<<dim3(LSEQ / 64, BSZ * NHEAD), 256>>>(qkvp, yp);
    // Output projection: [8192,1024] @ [1024,1024] + b
    gemm_tc<<<dim3(DMOD / 128, MROWS / 128), 256, GEMM_SMEM>>>(
        yp, Wproj, bproj, out, MROWS, DMOD, DMOD);
}

// round 6
// speedup vs baseline: 2.5542x; 1.6631x over previous
#include <cuda_runtime.h>
#include <cuda_bf16.h>
#include <math.h>
#include <stdint.h>

// Problem constants
#define BSZ   4
#define LSEQ  2048
#define DMOD  1024
#define NHEAD 16
#define HDIM  64
#define MROWS (BSZ * LSEQ)      // 8192
#define NQKV  (3 * DMOD)        // 3072

// Scratch (allocation-free rule: device globals)
__device__ float g_qkv[(size_t)MROWS * NQKV];   // [B*L, 3D]
__device__ float g_y[(size_t)MROWS * DMOD];     // attention output [B*L, D]

// ===========================================================================
// Helpers (plain sm_100-legal: cp.async, mma.sync, cvt.bf16)
// ===========================================================================
__device__ __forceinline__ uint32_t smem_u32(const void* p) {
    uint32_t a;
    asm("{ .reg .u64 t; cvta.to.shared.u64 t, %1; cvt.u32.u64 %0, t; }"
        : "=r"(a) : "l"(p));
    return a;
}
__device__ __forceinline__ void cp_async16(uint32_t dst, const void* src) {
    asm volatile("cp.async.cg.shared.global [%0], [%1], 16;"
                 :: "r"(dst), "l"(src) : "memory");
}
__device__ __forceinline__ void cp_commit() {
    asm volatile("cp.async.commit_group;" ::: "memory");
}
#define CP_WAIT(n) asm volatile("cp.async.wait_group %0;" :: "n"(n) : "memory")

__device__ __forceinline__ uint32_t f2tf32(float f) {
    uint32_t r;
    asm("cvt.rna.tf32.f32 %0, %1;" : "=r"(r) : "f"(f));
    return r;
}
__device__ __forceinline__ void mma_tf32(float* c, const uint32_t* a, const uint32_t* b) {
    asm volatile(
        "mma.sync.aligned.m16n8k8.row.col.f32.tf32.tf32.f32 "
        "{%0,%1,%2,%3}, {%4,%5,%6,%7}, {%8,%9}, {%0,%1,%2,%3};\n"
        : "+f"(c[0]), "+f"(c[1]), "+f"(c[2]), "+f"(c[3])
        : "r"(a[0]), "r"(a[1]), "r"(a[2]), "r"(a[3]), "r"(b[0]), "r"(b[1]));
}

// pack two floats to bf16x2: x -> low half, y -> high half
__device__ __forceinline__ uint32_t pk_bf16(float x, float y) {
    uint32_t r;
    asm("cvt.rn.bf16x2.f32 %0, %1, %2;" : "=r"(r) : "f"(y), "f"(x));
    return r;
}
__device__ __forceinline__ float bflo(uint32_t u) { return __uint_as_float(u << 16); }
__device__ __forceinline__ float bfhi(uint32_t u) { return __uint_as_float(u & 0xffff0000u); }

__device__ __forceinline__ void mma_bf16(float* c, const uint32_t* a,
                                         uint32_t b0, uint32_t b1) {
    asm volatile(
        "mma.sync.aligned.m16n8k16.row.col.f32.bf16.bf16.f32 "
        "{%0,%1,%2,%3}, {%4,%5,%6,%7}, {%8,%9}, {%0,%1,%2,%3};\n"
        : "+f"(c[0]), "+f"(c[1]), "+f"(c[2]), "+f"(c[3])
        : "r"(a[0]), "r"(a[1]), "r"(a[2]), "r"(a[3]), "r"(b0), "r"(b1));
}

// ===========================================================================
// tf32 tensor-core GEMM + bias (unchanged from round-5 passing kernel)
// ===========================================================================
#define GSTAGES 4
#define GBK 16
#define A_ST_F (128 * 20)
#define B_ST_F (16 * 136)
#define ST_F   (A_ST_F + B_ST_F)
#define GEMM_SMEM (GSTAGES * ST_F * 4)

__global__ __launch_bounds__(256, 1)
void gemm_tc(const float* __restrict__ A, const float* __restrict__ W,
             const float* __restrict__ bias, float* __restrict__ C,
             int M, int N, int K)
{
    extern __shared__ __align__(16) float sm_f[];
    const uint32_t sm_b = smem_u32(sm_f);

    const int tid  = threadIdx.x;
    const int wid  = tid >> 5;
    const int lane = tid & 31;
    const int grp  = lane >> 2;
    const int qid  = lane & 3;
    const int wm   = wid >> 2;
    const int wn   = wid & 3;
    const int m0   = blockIdx.y * 128;
    const int n0   = blockIdx.x * 128;
    const int NCHUNK = K / GBK;

    float acc[4][4][4];
    #pragma unroll
    for (int mi = 0; mi < 4; mi++)
        #pragma unroll
        for (int ni = 0; ni < 4; ni++)
            #pragma unroll
            for (int q = 0; q < 4; q++) acc[mi][ni][q] = 0.0f;

    auto load_stage = [&](int s, int k0) {
        const uint32_t as = sm_b + s * (ST_F * 4);
        const uint32_t bs = as + A_ST_F * 4;
        #pragma unroll
        for (int i = 0; i < 2; i++) {
            int id  = tid + i * 256;
            int row = id >> 2;
            int ch  = id & 3;
            cp_async16(as + row * 80 + ch * 16,
                       A + (size_t)(m0 + row) * K + k0 + ch * 4);
        }
        #pragma unroll
        for (int i = 0; i < 2; i++) {
            int id  = tid + i * 256;
            int row = id >> 5;
            int ch  = id & 31;
            cp_async16(bs + row * 544 + ch * 16,
                       W + (size_t)(k0 + row) * N + n0 + ch * 4);
        }
        cp_commit();
    };

    #pragma unroll
    for (int s = 0; s < GSTAGES - 1; s++) load_stage(s, s * GBK);

    for (int c = 0; c < NCHUNK; c++) {
        CP_WAIT(GSTAGES - 2);
        __syncthreads();
        {
            int nc = c + GSTAGES - 1;
            if (nc < NCHUNK) load_stage(nc % GSTAGES, nc * GBK);
        }

        const float* as = sm_f + (c % GSTAGES) * ST_F;
        const float* bs = as + A_ST_F;

        #pragma unroll
        for (int ks = 0; ks < 2; ks++) {
            const int kc = ks * 8;
            uint32_t af[4][4], bf[4][2];
            #pragma unroll
            for (int mi = 0; mi < 4; mi++) {
                int r = wm * 64 + mi * 16 + grp;
                int cc = kc + qid;
                af[mi][0] = f2tf32(as[r * 20 + cc]);
                af[mi][1] = f2tf32(as[(r + 8) * 20 + cc]);
                af[mi][2] = f2tf32(as[r * 20 + cc + 4]);
                af[mi][3] = f2tf32(as[(r + 8) * 20 + cc + 4]);
            }
            #pragma unroll
            for (int ni = 0; ni < 4; ni++) {
                int n = wn * 32 + ni * 8 + grp;
                int kk = kc + qid;
                bf[ni][0] = f2tf32(bs[kk * 136 + n]);
                bf[ni][1] = f2tf32(bs[(kk + 4) * 136 + n]);
            }
            #pragma unroll
            for (int mi = 0; mi < 4; mi++)
                #pragma unroll
                for (int ni = 0; ni < 4; ni++)
                    mma_tf32(acc[mi][ni], af[mi], bf[ni]);
        }
        __syncthreads();
    }

    #pragma unroll
    for (int mi = 0; mi < 4; mi++) {
        int r0 = m0 + wm * 64 + mi * 16 + grp;
        #pragma unroll
        for (int ni = 0; ni < 4; ni++) {
            int col = n0 + wn * 32 + ni * 8 + qid * 2;
            float2 bv = *(const float2*)&bias[col];
            float2 o0, o1;
            o0.x = acc[mi][ni][0] + bv.x;  o0.y = acc[mi][ni][1] + bv.y;
            o1.x = acc[mi][ni][2] + bv.x;  o1.y = acc[mi][ni][3] + bv.y;
            *(float2*)&C[(size_t)r0 * N + col]       = o0;
            *(float2*)&C[(size_t)(r0 + 8) * N + col] = o1;
        }
    }
}

// ===========================================================================
// Flash-attention (causal) with bf16 3-term mma.sync.
// Block = 128 threads (4 warps), q-tile 64 (16 rows/warp), k-tile 64.
// K smem: [j][d] bf16 hi/lo, row pitch 72 elems (36 words) -> conflict-free.
// V smem: transposed [d][j] bf16 hi/lo, same pitch.
// P never touches smem (S accum frags repacked to A frags in registers).
// ===========================================================================
__global__ __launch_bounds__(128, 3)
void attn_mma(const float* __restrict__ qkv, float* __restrict__ y)
{
    __shared__ __align__(16) uint32_t Khi[64 * 36];
    __shared__ __align__(16) uint32_t Klo[64 * 36];
    __shared__ __align__(16) __nv_bfloat16 Vthi[64 * 72];
    __shared__ __align__(16) __nv_bfloat16 Vtlo[64 * 72];

    const int tid  = threadIdx.x;
    const int wid  = tid >> 5;
    const int lane = tid & 31;
    const int grp  = lane >> 2;     // 0..7
    const int qid  = lane & 3;      // 0..3

    const int qt = gridDim.x - 1 - blockIdx.x;   // long rows first
    const int bh = blockIdx.y;
    const int b  = bh >> 4;
    const int h  = bh & 15;
    const int q0 = qt * 64;

    const float* base = qkv + (size_t)(b * LSEQ) * NQKV + h * HDIM;

    // ---- Load Q fragments (hi/lo bf16), rows wid*16+grp / +8 ----
    uint32_t qh[4][4], ql[4][4];
    const int i0 = q0 + wid * 16 + grp;   // global q row for c0/c1
    #pragma unroll
    for (int kc = 0; kc < 4; kc++)
        #pragma unroll
        for (int hh = 0; hh < 2; hh++)
            #pragma unroll
            for (int rr = 0; rr < 2; rr++) {
                const float* p = base + (size_t)(i0 + 8 * rr) * NQKV
                               + kc * 16 + hh * 8 + 2 * qid;
                float2 v = *(const float2*)p;
                uint32_t hi = pk_bf16(v.x, v.y);
                float lx = v.x - bflo(hi);
                float ly = v.y - bfhi(hi);
                qh[kc][2 * hh + rr] = hi;
                ql[kc][2 * hh + rr] = pk_bf16(lx, ly);
            }

    float o[8][4];
    #pragma unroll
    for (int nt = 0; nt < 8; nt++)
        #pragma unroll
        for (int c = 0; c < 4; c++) o[nt][c] = 0.0f;
    float m0f = -1e30f, m1f = -1e30f, l0 = 0.0f, l1 = 0.0f;

    for (int kt = 0; kt <= qt; kt++) {
        const int k0 = kt * 64;

        // ---- Load K (hi/lo words) and V (transposed hi/lo) ----
        {
            const int j  = tid >> 1;
            const int dh = (tid & 1) * 32;
            const float* kr = base + DMOD     + (size_t)(k0 + j) * NQKV + dh;
            const float* vr = base + 2 * DMOD + (size_t)(k0 + j) * NQKV + dh;
            const int wbase = j * 36 + dh / 2;
            #pragma unroll
            for (int i = 0; i < 8; i++) {
                float4 kv = *(const float4*)&kr[4 * i];
                uint32_t h0 = pk_bf16(kv.x, kv.y);
                uint32_t h1 = pk_bf16(kv.z, kv.w);
                Khi[wbase + 2 * i]     = h0;
                Khi[wbase + 2 * i + 1] = h1;
                Klo[wbase + 2 * i]     = pk_bf16(kv.x - bflo(h0), kv.y - bfhi(h0));
                Klo[wbase + 2 * i + 1] = pk_bf16(kv.z - bflo(h1), kv.w - bfhi(h1));

                float4 vv = *(const float4*)&vr[4 * i];
                const int d = dh + 4 * i;
                float va[4] = {vv.x, vv.y, vv.z, vv.w};
                #pragma unroll
                for (int e = 0; e < 4; e++) {
                    __nv_bfloat16 hb = __float2bfloat16(va[e]);
                    Vthi[(d + e) * 72 + j] = hb;
                    Vtlo[(d + e) * 72 + j] =
                        __float2bfloat16(va[e] - __bfloat162float(hb));
                }
            }
        }
        __syncthreads();

        // ---- S = Q @ K^T (3-term bf16) ----
        float s[8][4];
        #pragma unroll
        for (int nt = 0; nt < 8; nt++)
            #pragma unroll
            for (int c = 0; c < 4; c++) s[nt][c] = 0.0f;

        #pragma unroll
        for (int nt = 0; nt < 8; nt++) {
            const int krow = (nt * 8 + grp) * 36;
            #pragma unroll
            for (int kc = 0; kc < 4; kc++) {
                uint32_t b0h = Khi[krow + 8 * kc + qid];
                uint32_t b1h = Khi[krow + 8 * kc + 4 + qid];
                uint32_t b0l = Klo[krow + 8 * kc + qid];
                uint32_t b1l = Klo[krow + 8 * kc + 4 + qid];
                mma_bf16(s[nt], qh[kc], b0h, b1h);
                mma_bf16(s[nt], qh[kc], b0l, b1l);
                mma_bf16(s[nt], ql[kc], b0h, b1h);
            }
        }

        // ---- scale + causal mask ----
        const float scale = 0.125f;
        if (kt == qt) {
            #pragma unroll
            for (int nt = 0; nt < 8; nt++)
                #pragma unroll
                for (int c = 0; c < 4; c++) {
                    int j = k0 + nt * 8 + 2 * qid + (c & 1);
                    int i = (c < 2) ? i0 : (i0 + 8);
                    float sv = s[nt][c] * scale;
                    if (j > i) sv = -1e30f;
                    s[nt][c] = sv;
                }
        } else {
            #pragma unroll
            for (int nt = 0; nt < 8; nt++)
                #pragma unroll
                for (int c = 0; c < 4; c++) s[nt][c] *= scale;
        }

        // ---- online softmax: row max ----
        float mx0 = -1e30f, mx1 = -1e30f;
        #pragma unroll
        for (int nt = 0; nt < 8; nt++) {
            mx0 = fmaxf(mx0, fmaxf(s[nt][0], s[nt][1]));
            mx1 = fmaxf(mx1, fmaxf(s[nt][2], s[nt][3]));
        }
        #pragma unroll
        for (int off = 1; off <= 2; off <<= 1) {
            mx0 = fmaxf(mx0, __shfl_xor_sync(0xffffffffu, mx0, off));
            mx1 = fmaxf(mx1, __shfl_xor_sync(0xffffffffu, mx1, off));
        }
        float mn0 = fmaxf(m0f, mx0);
        float mn1 = fmaxf(m1f, mx1);
        float a0 = __expf(m0f - mn0);
        float a1 = __expf(m1f - mn1);
        m0f = mn0; m1f = mn1;
        #pragma unroll
        for (int nt = 0; nt < 8; nt++) {
            o[nt][0] *= a0;  o[nt][1] *= a0;
            o[nt][2] *= a1;  o[nt][3] *= a1;
        }

        // ---- exp, repack P to A frags per k-chunk, PV mma (3-term) ----
        float rs0 = 0.0f, rs1 = 0.0f;
        #pragma unroll
        for (int kc2 = 0; kc2 < 4; kc2++) {
            uint32_t ph[4], pl[4];
            #pragma unroll
            for (int part = 0; part < 2; part++) {
                const int nt = kc2 * 2 + part;
                float p0 = __expf(s[nt][0] - mn0);
                float p1 = __expf(s[nt][1] - mn0);
                float p2 = __expf(s[nt][2] - mn1);
                float p3 = __expf(s[nt][3] - mn1);
                rs0 += p0 + p1;
                rs1 += p2 + p3;
                uint32_t u01 = pk_bf16(p0, p1);
                uint32_t u23 = pk_bf16(p2, p3);
                ph[2 * part]     = u01;
                ph[2 * part + 1] = u23;
                pl[2 * part]     = pk_bf16(p0 - bflo(u01), p1 - bfhi(u01));
                pl[2 * part + 1] = pk_bf16(p2 - bflo(u23), p3 - bfhi(u23));
            }
            const uint32_t* VhW = (const uint32_t*)Vthi;
            const uint32_t* VlW = (const uint32_t*)Vtlo;
            #pragma unroll
            for (int ont = 0; ont < 8; ont++) {
                const int vrow = (ont * 8 + grp) * 36;
                uint32_t b0h = VhW[vrow + 8 * kc2 + qid];
                uint32_t b1h = VhW[vrow + 8 * kc2 + 4 + qid];
                uint32_t b0l = VlW[vrow + 8 * kc2 + qid];
                uint32_t b1l = VlW[vrow + 8 * kc2 + 4 + qid];
                mma_bf16(o[ont], ph, b0h, b1h);
                mma_bf16(o[ont], ph, b0l, b1l);
                mma_bf16(o[ont], pl, b0h, b1h);
            }
        }
        #pragma unroll
        for (int off = 1; off <= 2; off <<= 1) {
            rs0 += __shfl_xor_sync(0xffffffffu, rs0, off);
            rs1 += __shfl_xor_sync(0xffffffffu, rs1, off);
        }
        l0 = l0 * a0 + rs0;
        l1 = l1 * a1 + rs1;

        __syncthreads();   // before next tile overwrites K/V smem
    }

    // ---- epilogue ----
    const float inv0 = 1.0f / l0;
    const float inv1 = 1.0f / l1;
    #pragma unroll
    for (int ont = 0; ont < 8; ont++) {
        int col = h * HDIM + ont * 8 + 2 * qid;
        float2 v0 = make_float2(o[ont][0] * inv0, o[ont][1] * inv0);
        float2 v1 = make_float2(o[ont][2] * inv1, o[ont][3] * inv1);
        *(float2*)&y[(size_t)(b * LSEQ + i0) * DMOD + col]     = v0;
        *(float2*)&y[(size_t)(b * LSEQ + i0 + 8) * DMOD + col] = v1;
    }
}

// ===========================================================================
// Launch
// ===========================================================================
extern "C" void kernel_launch(void* const* d_in, const int* in_sizes, int n_in,
                              void* d_out, int out_size)
{
    (void)in_sizes; (void)n_in; (void)out_size;
    const float* x     = (const float*)d_in[0];
    const float* Wqkv  = (const float*)d_in[1];
    const float* bqkv  = (const float*)d_in[2];
    const float* Wproj = (const float*)d_in[3];
    const float* bproj = (const float*)d_in[4];
    float* out = (float*)d_out;

    float* qkvp = nullptr;
    float* yp   = nullptr;
    cudaGetSymbolAddress((void**)&qkvp, g_qkv);
    cudaGetSymbolAddress((void**)&yp, g_y);

    static bool attr_set = false;
    if (!attr_set) {
        cudaFuncSetAttribute(gemm_tc, cudaFuncAttributeMaxDynamicSharedMemorySize,
                             GEMM_SMEM);
        attr_set = true;
    }

    // QKV projection: [8192,1024] @ [1024,3072] + b
    gemm_tc<<<dim3(NQKV / 128, MROWS / 128), 256, GEMM_SMEM>>>(
        x, Wqkv, bqkv, qkvp, MROWS, NQKV, DMOD);
    // Causal flash attention (bf16 3-term mma)
    attn_mma<<<dim3(LSEQ / 64, BSZ * NHEAD), 128>>>(qkvp, yp);
    // Output projection: [8192,1024] @ [1024,1024] + b
    gemm_tc<<<dim3(DMOD / 128, MROWS / 128), 256, GEMM_SMEM>>>(
        yp, Wproj, bproj, out, MROWS, DMOD, DMOD);
}

// round 8
// speedup vs baseline: 2.8340x; 1.1095x over previous
#include <cuda_runtime.h>
#include <cuda_bf16.h>
#include <math.h>
#include <stdint.h>

// Problem constants
#define BSZ   4
#define LSEQ  2048
#define DMOD  1024
#define NHEAD 16
#define HDIM  64
#define MROWS (BSZ * LSEQ)      // 8192
#define NQKV  (3 * DMOD)        // 3072

// Scratch (allocation-free rule: device globals)
__device__ float g_qkv[(size_t)MROWS * NQKV];   // [B*L, 3D]
__device__ float g_y[(size_t)MROWS * DMOD];     // attention output [B*L, D]

// ===========================================================================
// Helpers (plain sm_100-legal: cp.async, mma.sync, cvt.bf16)
// ===========================================================================
__device__ __forceinline__ uint32_t smem_u32(const void* p) {
    uint32_t a;
    asm("{ .reg .u64 t; cvta.to.shared.u64 t, %1; cvt.u32.u64 %0, t; }"
        : "=r"(a) : "l"(p));
    return a;
}
__device__ __forceinline__ void cp_async16(uint32_t dst, const void* src) {
    asm volatile("cp.async.cg.shared.global [%0], [%1], 16;"
                 :: "r"(dst), "l"(src) : "memory");
}
__device__ __forceinline__ void cp_commit() {
    asm volatile("cp.async.commit_group;" ::: "memory");
}
#define CP_WAIT(n) asm volatile("cp.async.wait_group %0;" :: "n"(n) : "memory")

__device__ __forceinline__ uint32_t f2tf32(float f) {
    uint32_t r;
    asm("cvt.rna.tf32.f32 %0, %1;" : "=r"(r) : "f"(f));
    return r;
}
__device__ __forceinline__ void mma_tf32(float* c, const uint32_t* a, const uint32_t* b) {
    asm volatile(
        "mma.sync.aligned.m16n8k8.row.col.f32.tf32.tf32.f32 "
        "{%0,%1,%2,%3}, {%4,%5,%6,%7}, {%8,%9}, {%0,%1,%2,%3};\n"
        : "+f"(c[0]), "+f"(c[1]), "+f"(c[2]), "+f"(c[3])
        : "r"(a[0]), "r"(a[1]), "r"(a[2]), "r"(a[3]), "r"(b[0]), "r"(b[1]));
}

// pack two floats to bf16x2: x -> low half, y -> high half
__device__ __forceinline__ uint32_t pk_bf16(float x, float y) {
    uint32_t r;
    asm("cvt.rn.bf16x2.f32 %0, %1, %2;" : "=r"(r) : "f"(y), "f"(x));
    return r;
}
__device__ __forceinline__ float bflo(uint32_t u) { return __uint_as_float(u << 16); }
__device__ __forceinline__ float bfhi(uint32_t u) { return __uint_as_float(u & 0xffff0000u); }

__device__ __forceinline__ void mma_bf16(float* c, const uint32_t* a,
                                         uint32_t b0, uint32_t b1) {
    asm volatile(
        "mma.sync.aligned.m16n8k16.row.col.f32.bf16.bf16.f32 "
        "{%0,%1,%2,%3}, {%4,%5,%6,%7}, {%8,%9}, {%0,%1,%2,%3};\n"
        : "+f"(c[0]), "+f"(c[1]), "+f"(c[2]), "+f"(c[3])
        : "r"(a[0]), "r"(a[1]), "r"(a[2]), "r"(a[3]), "r"(b0), "r"(b1));
}

// Conflict-free column swizzle: 5-bit bijection of row XOR'd into 5-bit col.
__device__ __forceinline__ int swz(int col, int row) {
    return col ^ (((row & 7) << 2) | ((row >> 3) & 3));
}

// ===========================================================================
// tf32 tensor-core GEMM + bias (unchanged passing kernel)
// ===========================================================================
#define GSTAGES 4
#define GBK 16
#define A_ST_F (128 * 20)
#define B_ST_F (16 * 136)
#define ST_F   (A_ST_F + B_ST_F)
#define GEMM_SMEM (GSTAGES * ST_F * 4)

__global__ __launch_bounds__(256, 1)
void gemm_tc(const float* __restrict__ A, const float* __restrict__ W,
             const float* __restrict__ bias, float* __restrict__ C,
             int M, int N, int K)
{
    extern __shared__ __align__(16) float sm_f[];
    const uint32_t sm_b = smem_u32(sm_f);

    const int tid  = threadIdx.x;
    const int wid  = tid >> 5;
    const int lane = tid & 31;
    const int grp  = lane >> 2;
    const int qid  = lane & 3;
    const int wm   = wid >> 2;
    const int wn   = wid & 3;
    const int m0   = blockIdx.y * 128;
    const int n0   = blockIdx.x * 128;
    const int NCHUNK = K / GBK;

    float acc[4][4][4];
    #pragma unroll
    for (int mi = 0; mi < 4; mi++)
        #pragma unroll
        for (int ni = 0; ni < 4; ni++)
            #pragma unroll
            for (int q = 0; q < 4; q++) acc[mi][ni][q] = 0.0f;

    auto load_stage = [&](int s, int k0) {
        const uint32_t as = sm_b + s * (ST_F * 4);
        const uint32_t bs = as + A_ST_F * 4;
        #pragma unroll
        for (int i = 0; i < 2; i++) {
            int id  = tid + i * 256;
            int row = id >> 2;
            int ch  = id & 3;
            cp_async16(as + row * 80 + ch * 16,
                       A + (size_t)(m0 + row) * K + k0 + ch * 4);
        }
        #pragma unroll
        for (int i = 0; i < 2; i++) {
            int id  = tid + i * 256;
            int row = id >> 5;
            int ch  = id & 31;
            cp_async16(bs + row * 544 + ch * 16,
                       W + (size_t)(k0 + row) * N + n0 + ch * 4);
        }
        cp_commit();
    };

    #pragma unroll
    for (int s = 0; s < GSTAGES - 1; s++) load_stage(s, s * GBK);

    for (int c = 0; c < NCHUNK; c++) {
        CP_WAIT(GSTAGES - 2);
        __syncthreads();
        {
            int nc = c + GSTAGES - 1;
            if (nc < NCHUNK) load_stage(nc % GSTAGES, nc * GBK);
        }

        const float* as = sm_f + (c % GSTAGES) * ST_F;
        const float* bs = as + A_ST_F;

        #pragma unroll
        for (int ks = 0; ks < 2; ks++) {
            const int kc = ks * 8;
            uint32_t af[4][4], bf[4][2];
            #pragma unroll
            for (int mi = 0; mi < 4; mi++) {
                int r = wm * 64 + mi * 16 + grp;
                int cc = kc + qid;
                af[mi][0] = f2tf32(as[r * 20 + cc]);
                af[mi][1] = f2tf32(as[(r + 8) * 20 + cc]);
                af[mi][2] = f2tf32(as[r * 20 + cc + 4]);
                af[mi][3] = f2tf32(as[(r + 8) * 20 + cc + 4]);
            }
            #pragma unroll
            for (int ni = 0; ni < 4; ni++) {
                int n = wn * 32 + ni * 8 + grp;
                int kk = kc + qid;
                bf[ni][0] = f2tf32(bs[kk * 136 + n]);
                bf[ni][1] = f2tf32(bs[(kk + 4) * 136 + n]);
            }
            #pragma unroll
            for (int mi = 0; mi < 4; mi++)
                #pragma unroll
                for (int ni = 0; ni < 4; ni++)
                    mma_tf32(acc[mi][ni], af[mi], bf[ni]);
        }
        __syncthreads();
    }

    #pragma unroll
    for (int mi = 0; mi < 4; mi++) {
        int r0 = m0 + wm * 64 + mi * 16 + grp;
        #pragma unroll
        for (int ni = 0; ni < 4; ni++) {
            int col = n0 + wn * 32 + ni * 8 + qid * 2;
            float2 bv = *(const float2*)&bias[col];
            float2 o0, o1;
            o0.x = acc[mi][ni][0] + bv.x;  o0.y = acc[mi][ni][1] + bv.y;
            o1.x = acc[mi][ni][2] + bv.x;  o1.y = acc[mi][ni][3] + bv.y;
            *(float2*)&C[(size_t)r0 * N + col]       = o0;
            *(float2*)&C[(size_t)(r0 + 8) * N + col] = o1;
        }
    }
}

// ===========================================================================
// Flash-attention (causal), bf16 3-term mma.sync.
// Round-8: fixed V staging pitch 66 -> 68 (16B alignment for cp.async and
// float4 LDS; round-7 trap). MMA-path swizzle unchanged (conflict-free).
// ===========================================================================
// Dynamic smem layout (float/word units):
#define AT_KST   0                      // fp32 K staging: 64 x 68
#define AT_VST   (64 * 68)              // fp32 V staging: 64 x 68 (16B-aligned rows)
#define AT_KHI   (AT_VST + 64 * 68)     // bf16x2 words: 64 rows x 32
#define AT_KLO   (AT_KHI + 2048)
#define AT_VHI   (AT_KLO + 2048)
#define AT_VLO   (AT_VHI + 2048)
#define ATTN_SMEM ((AT_VLO + 2048) * 4) // 67584 bytes

__global__ __launch_bounds__(128, 3)
void attn_mma(const float* __restrict__ qkv, float* __restrict__ y)
{
    extern __shared__ __align__(16) float asm_f[];
    float*    Kst  = asm_f + AT_KST;
    float*    Vst  = asm_f + AT_VST;
    uint32_t* KhiW = (uint32_t*)(asm_f + AT_KHI);
    uint32_t* KloW = (uint32_t*)(asm_f + AT_KLO);
    uint32_t* VhW  = (uint32_t*)(asm_f + AT_VHI);
    uint32_t* VlW  = (uint32_t*)(asm_f + AT_VLO);
    const uint32_t sKst = smem_u32(Kst);
    const uint32_t sVst = smem_u32(Vst);

    const int tid  = threadIdx.x;
    const int wid  = tid >> 5;
    const int lane = tid & 31;
    const int grp  = lane >> 2;     // 0..7
    const int qid  = lane & 3;      // 0..3

    const int qt = gridDim.x - 1 - blockIdx.x;   // long rows first
    const int bh = blockIdx.y;
    const int b  = bh >> 4;
    const int h  = bh & 15;
    const int q0 = qt * 64;

    const float* base = qkv + (size_t)(b * LSEQ) * NQKV + h * HDIM;

    // ---- Load Q fragments (hi/lo bf16), rows wid*16+grp / +8 ----
    uint32_t qh[4][4], ql[4][4];
    const int i0 = q0 + wid * 16 + grp;
    #pragma unroll
    for (int kc = 0; kc < 4; kc++)
        #pragma unroll
        for (int hh = 0; hh < 2; hh++)
            #pragma unroll
            for (int rr = 0; rr < 2; rr++) {
                const float* p = base + (size_t)(i0 + 8 * rr) * NQKV
                               + kc * 16 + hh * 8 + 2 * qid;
                float2 v = *(const float2*)p;
                uint32_t hi = pk_bf16(v.x, v.y);
                qh[kc][2 * hh + rr] = hi;
                ql[kc][2 * hh + rr] = pk_bf16(v.x - bflo(hi), v.y - bfhi(hi));
            }

    float o[8][4];
    #pragma unroll
    for (int nt = 0; nt < 8; nt++)
        #pragma unroll
        for (int c = 0; c < 4; c++) o[nt][c] = 0.0f;
    float m0f = -1e30f, m1f = -1e30f, l0 = 0.0f, l1 = 0.0f;

    // ---- staged prefetch of K/V fp32 tiles (68-float pitch, 16B-aligned) ----
    auto prefetch = [&](int kt) {
        const int k0 = kt * 64;
        #pragma unroll
        for (int i = 0; i < 8; i++) {
            int id  = tid + 128 * i;
            int row = id >> 4;
            int ch  = id & 15;
            const float* kr = base + DMOD     + (size_t)(k0 + row) * NQKV + ch * 4;
            const float* vr = base + 2 * DMOD + (size_t)(k0 + row) * NQKV + ch * 4;
            cp_async16(sKst + (row * 68 + ch * 4) * 4, kr);
            cp_async16(sVst + (row * 68 + ch * 4) * 4, vr);
        }
        cp_commit();
    };

    prefetch(0);

    for (int kt = 0; kt <= qt; kt++) {
        const int k0 = kt * 64;

        CP_WAIT(0);
        __syncthreads();   // staging ready AND previous tile's MMAs done

        // ---- convert K: staging fp32 -> swizzled bf16 hi/lo ----
        {
            const int j    = tid & 63;
            const int half = tid >> 6;           // 0/1
            const float* src = Kst + j * 68 + half * 32;
            uint32_t* dsh = KhiW + j * 32;
            uint32_t* dsl = KloW + j * 32;
            #pragma unroll
            for (int i = 0; i < 8; i++) {
                float4 k4 = *(const float4*)&src[4 * i];
                uint32_t h0 = pk_bf16(k4.x, k4.y);
                uint32_t h1 = pk_bf16(k4.z, k4.w);
                int c = half * 16 + 2 * i;
                dsh[swz(c, j)]     = h0;
                dsh[swz(c + 1, j)] = h1;
                dsl[swz(c, j)]     = pk_bf16(k4.x - bflo(h0), k4.y - bfhi(h0));
                dsl[swz(c + 1, j)] = pk_bf16(k4.z - bflo(h1), k4.w - bfhi(h1));
            }
        }
        // ---- convert V: staging fp32 -> transposed swizzled bf16 hi/lo ----
        {
            const int jp = tid & 31;             // j-pair 0..31
            const int d0 = (tid >> 5) << 4;      // 0,16,32,48
            const float* r0 = Vst + (2 * jp) * 68 + d0;
            const float* r1 = Vst + (2 * jp + 1) * 68 + d0;
            #pragma unroll
            for (int i4 = 0; i4 < 4; i4++) {
                float4 x = *(const float4*)&r0[4 * i4];
                float4 yv = *(const float4*)&r1[4 * i4];
                float xs[4] = {x.x, x.y, x.z, x.w};
                float ys[4] = {yv.x, yv.y, yv.z, yv.w};
                #pragma unroll
                for (int e = 0; e < 4; e++) {
                    int d = d0 + 4 * i4 + e;
                    uint32_t hi = pk_bf16(xs[e], ys[e]);
                    VhW[d * 32 + swz(jp, d)] = hi;
                    VlW[d * 32 + swz(jp, d)] =
                        pk_bf16(xs[e] - bflo(hi), ys[e] - bfhi(hi));
                }
            }
        }
        __syncthreads();   // bf16 buffers ready; staging free

        if (kt < qt) prefetch(kt + 1);   // overlap gmem with MMAs below

        // ---- S = Q @ K^T (3-term bf16) ----
        float s[8][4];
        #pragma unroll
        for (int nt = 0; nt < 8; nt++)
            #pragma unroll
            for (int c = 0; c < 4; c++) s[nt][c] = 0.0f;

        #pragma unroll
        for (int nt = 0; nt < 8; nt++) {
            const int j = nt * 8 + grp;
            const uint32_t* kh = KhiW + j * 32;
            const uint32_t* kl = KloW + j * 32;
            #pragma unroll
            for (int kc = 0; kc < 4; kc++) {
                uint32_t b0h = kh[swz(8 * kc + qid, j)];
                uint32_t b1h = kh[swz(8 * kc + 4 + qid, j)];
                uint32_t b0l = kl[swz(8 * kc + qid, j)];
                uint32_t b1l = kl[swz(8 * kc + 4 + qid, j)];
                mma_bf16(s[nt], qh[kc], b0h, b1h);
                mma_bf16(s[nt], qh[kc], b0l, b1l);
                mma_bf16(s[nt], ql[kc], b0h, b1h);
            }
        }

        // ---- scale + causal mask ----
        const float scale = 0.125f;
        if (kt == qt) {
            #pragma unroll
            for (int nt = 0; nt < 8; nt++)
                #pragma unroll
                for (int c = 0; c < 4; c++) {
                    int j = k0 + nt * 8 + 2 * qid + (c & 1);
                    int i = (c < 2) ? i0 : (i0 + 8);
                    float sv = s[nt][c] * scale;
                    if (j > i) sv = -1e30f;
                    s[nt][c] = sv;
                }
        } else {
            #pragma unroll
            for (int nt = 0; nt < 8; nt++)
                #pragma unroll
                for (int c = 0; c < 4; c++) s[nt][c] *= scale;
        }

        // ---- online softmax: row max ----
        float mx0 = -1e30f, mx1 = -1e30f;
        #pragma unroll
        for (int nt = 0; nt < 8; nt++) {
            mx0 = fmaxf(mx0, fmaxf(s[nt][0], s[nt][1]));
            mx1 = fmaxf(mx1, fmaxf(s[nt][2], s[nt][3]));
        }
        #pragma unroll
        for (int off = 1; off <= 2; off <<= 1) {
            mx0 = fmaxf(mx0, __shfl_xor_sync(0xffffffffu, mx0, off));
            mx1 = fmaxf(mx1, __shfl_xor_sync(0xffffffffu, mx1, off));
        }
        float mn0 = fmaxf(m0f, mx0);
        float mn1 = fmaxf(m1f, mx1);
        float a0 = __expf(m0f - mn0);
        float a1 = __expf(m1f - mn1);
        m0f = mn0; m1f = mn1;
        #pragma unroll
        for (int nt = 0; nt < 8; nt++) {
            o[nt][0] *= a0;  o[nt][1] *= a0;
            o[nt][2] *= a1;  o[nt][3] *= a1;
        }

        // ---- exp, repack P to A frags per k-chunk, PV mma (3-term) ----
        float rs0 = 0.0f, rs1 = 0.0f;
        #pragma unroll
        for (int kc2 = 0; kc2 < 4; kc2++) {
            uint32_t ph[4], pl[4];
            #pragma unroll
            for (int part = 0; part < 2; part++) {
                const int nt = kc2 * 2 + part;
                float p0 = __expf(s[nt][0] - mn0);
                float p1 = __expf(s[nt][1] - mn0);
                float p2 = __expf(s[nt][2] - mn1);
                float p3 = __expf(s[nt][3] - mn1);
                rs0 += p0 + p1;
                rs1 += p2 + p3;
                uint32_t u01 = pk_bf16(p0, p1);
                uint32_t u23 = pk_bf16(p2, p3);
                ph[2 * part]     = u01;
                ph[2 * part + 1] = u23;
                pl[2 * part]     = pk_bf16(p0 - bflo(u01), p1 - bfhi(u01));
                pl[2 * part + 1] = pk_bf16(p2 - bflo(u23), p3 - bfhi(u23));
            }
            #pragma unroll
            for (int ont = 0; ont < 8; ont++) {
                const int d = ont * 8 + grp;
                const uint32_t* vh = VhW + d * 32;
                const uint32_t* vl = VlW + d * 32;
                uint32_t b0h = vh[swz(8 * kc2 + qid, d)];
                uint32_t b1h = vh[swz(8 * kc2 + 4 + qid, d)];
                uint32_t b0l = vl[swz(8 * kc2 + qid, d)];
                uint32_t b1l = vl[swz(8 * kc2 + 4 + qid, d)];
                mma_bf16(o[ont], ph, b0h, b1h);
                mma_bf16(o[ont], ph, b0l, b1l);
                mma_bf16(o[ont], pl, b0h, b1h);
            }
        }
        #pragma unroll
        for (int off = 1; off <= 2; off <<= 1) {
            rs0 += __shfl_xor_sync(0xffffffffu, rs0, off);
            rs1 += __shfl_xor_sync(0xffffffffu, rs1, off);
        }
        l0 = l0 * a0 + rs0;
        l1 = l1 * a1 + rs1;
        // no trailing sync: top-of-loop sync protects bf16 buffers
    }

    // ---- epilogue ----
    const float inv0 = 1.0f / l0;
    const float inv1 = 1.0f / l1;
    #pragma unroll
    for (int ont = 0; ont < 8; ont++) {
        int col = h * HDIM + ont * 8 + 2 * qid;
        float2 v0 = make_float2(o[ont][0] * inv0, o[ont][1] * inv0);
        float2 v1 = make_float2(o[ont][2] * inv1, o[ont][3] * inv1);
        *(float2*)&y[(size_t)(b * LSEQ + i0) * DMOD + col]     = v0;
        *(float2*)&y[(size_t)(b * LSEQ + i0 + 8) * DMOD + col] = v1;
    }
}

// ===========================================================================
// Launch
// ===========================================================================
extern "C" void kernel_launch(void* const* d_in, const int* in_sizes, int n_in,
                              void* d_out, int out_size)
{
    (void)in_sizes; (void)n_in; (void)out_size;
    const float* x     = (const float*)d_in[0];
    const float* Wqkv  = (const float*)d_in[1];
    const float* bqkv  = (const float*)d_in[2];
    const float* Wproj = (const float*)d_in[3];
    const float* bproj = (const float*)d_in[4];
    float* out = (float*)d_out;

    float* qkvp = nullptr;
    float* yp   = nullptr;
    cudaGetSymbolAddress((void**)&qkvp, g_qkv);
    cudaGetSymbolAddress((void**)&yp, g_y);

    static bool attr_set = false;
    if (!attr_set) {
        cudaFuncSetAttribute(gemm_tc, cudaFuncAttributeMaxDynamicSharedMemorySize,
                             GEMM_SMEM);
        cudaFuncSetAttribute(attn_mma, cudaFuncAttributeMaxDynamicSharedMemorySize,
                             ATTN_SMEM);
        attr_set = true;
    }

    // QKV projection: [8192,1024] @ [1024,3072] + b
    gemm_tc<<<dim3(NQKV / 128, MROWS / 128), 256, GEMM_SMEM>>>(
        x, Wqkv, bqkv, qkvp, MROWS, NQKV, DMOD);
    // Causal flash attention (bf16 3-term mma, swizzled + staged)
    attn_mma<<<dim3(LSEQ / 64, BSZ * NHEAD), 128, ATTN_SMEM>>>(qkvp, yp);
    // Output projection: [8192,1024] @ [1024,1024] + b
    gemm_tc<<<dim3(DMOD / 128, MROWS / 128), 256, GEMM_SMEM>>>(
        yp, Wproj, bproj, out, MROWS, DMOD, DMOD);
}

// round 9
// speedup vs baseline: 2.8710x; 1.0131x over previous
#include <cuda_runtime.h>
#include <cuda_bf16.h>
#include <math.h>
#include <stdint.h>

// Problem constants
#define BSZ   4
#define LSEQ  2048
#define DMOD  1024
#define NHEAD 16
#define HDIM  64
#define MROWS (BSZ * LSEQ)      // 8192
#define NQKV  (3 * DMOD)        // 3072

// Scratch (allocation-free rule: device globals)
__device__ __align__(16) float g_qkv[(size_t)MROWS * NQKV];   // [B*L, 3D]
__device__ __align__(16) float g_y[(size_t)MROWS * DMOD];     // attn out (tf32-rounded)
__device__ __align__(16) float g_xr[(size_t)MROWS * DMOD];        // x, tf32-rounded
__device__ __align__(16) float g_wqkvr[(size_t)DMOD * NQKV];      // Wqkv, rounded
__device__ __align__(16) float g_wprojr[(size_t)DMOD * DMOD];     // Wproj, rounded
// Pre-converted KV: per (bh, jtile): [Khi 2048w][Klo 2048w], swizzled tiles
__device__ __align__(16) uint32_t g_kw[(size_t)64 * 32 * 2 * 2048];
__device__ __align__(16) uint32_t g_vw[(size_t)64 * 32 * 2 * 2048];

// ===========================================================================
// Helpers
// ===========================================================================
__device__ __forceinline__ uint32_t smem_u32(const void* p) {
    uint32_t a;
    asm("{ .reg .u64 t; cvta.to.shared.u64 t, %1; cvt.u32.u64 %0, t; }"
        : "=r"(a) : "l"(p));
    return a;
}
__device__ __forceinline__ void cp_async16(uint32_t dst, const void* src) {
    asm volatile("cp.async.cg.shared.global [%0], [%1], 16;"
                 :: "r"(dst), "l"(src) : "memory");
}
__device__ __forceinline__ void cp_commit() {
    asm volatile("cp.async.commit_group;" ::: "memory");
}
#define CP_WAIT(n) asm volatile("cp.async.wait_group %0;" :: "n"(n) : "memory")

__device__ __forceinline__ uint32_t f2tf32(float f) {
    uint32_t r;
    asm("cvt.rna.tf32.f32 %0, %1;" : "=r"(r) : "f"(f));
    return r;
}
__device__ __forceinline__ void mma_tf32(float* c, const uint32_t* a, const uint32_t* b) {
    asm volatile(
        "mma.sync.aligned.m16n8k8.row.col.f32.tf32.tf32.f32 "
        "{%0,%1,%2,%3}, {%4,%5,%6,%7}, {%8,%9}, {%0,%1,%2,%3};\n"
        : "+f"(c[0]), "+f"(c[1]), "+f"(c[2]), "+f"(c[3])
        : "r"(a[0]), "r"(a[1]), "r"(a[2]), "r"(a[3]), "r"(b[0]), "r"(b[1]));
}
__device__ __forceinline__ uint32_t pk_bf16(float x, float y) {
    uint32_t r;
    asm("cvt.rn.bf16x2.f32 %0, %1, %2;" : "=r"(r) : "f"(y), "f"(x));
    return r;
}
__device__ __forceinline__ float bflo(uint32_t u) { return __uint_as_float(u << 16); }
__device__ __forceinline__ float bfhi(uint32_t u) { return __uint_as_float(u & 0xffff0000u); }

__device__ __forceinline__ void mma_bf16(float* c, const uint32_t* a,
                                         uint32_t b0, uint32_t b1) {
    asm volatile(
        "mma.sync.aligned.m16n8k16.row.col.f32.bf16.bf16.f32 "
        "{%0,%1,%2,%3}, {%4,%5,%6,%7}, {%8,%9}, {%0,%1,%2,%3};\n"
        : "+f"(c[0]), "+f"(c[1]), "+f"(c[2]), "+f"(c[3])
        : "r"(a[0]), "r"(a[1]), "r"(a[2]), "r"(a[3]), "r"(b0), "r"(b1));
}
__device__ __forceinline__ int swz(int col, int row) {
    return col ^ (((row & 7) << 2) | ((row >> 3) & 3));
}

// ===========================================================================
// Pre-pass 1: elementwise tf32(rna) rounding
// ===========================================================================
__global__ void round_tf32_kernel(const float* __restrict__ in,
                                  float* __restrict__ out, int n4)
{
    int i = blockIdx.x * blockDim.x + threadIdx.x;
    if (i < n4) {
        float4 v = ((const float4*)in)[i];
        v.x = __uint_as_float(f2tf32(v.x));
        v.y = __uint_as_float(f2tf32(v.y));
        v.z = __uint_as_float(f2tf32(v.z));
        v.w = __uint_as_float(f2tf32(v.w));
        ((float4*)out)[i] = v;
    }
}

// ===========================================================================
// Pre-pass 2: K/V fp32 -> swizzled bf16 hi/lo gmem tiles
// grid (32 jtiles, 64 bh), 128 threads. Same layout the attn MMA frags read.
// ===========================================================================
__global__ __launch_bounds__(128)
void kvconv_kernel(const float* __restrict__ qkv,
                   uint32_t* __restrict__ kw, uint32_t* __restrict__ vw)
{
    const int tid = threadIdx.x;
    const int jt  = blockIdx.x;
    const int bh  = blockIdx.y;
    const int b   = bh >> 4;
    const int h   = bh & 15;
    const int k0  = jt * 64;
    const float* base = qkv + (size_t)(b * LSEQ) * NQKV + h * HDIM;

    uint32_t* kh = kw + ((size_t)(bh * 32 + jt) * 2) * 2048;
    uint32_t* kl = kh + 2048;
    uint32_t* vh = vw + ((size_t)(bh * 32 + jt) * 2) * 2048;
    uint32_t* vl = vh + 2048;

    // K: j = tid&63, half = tid>>6
    {
        const int j    = tid & 63;
        const int half = tid >> 6;
        const float* src = base + DMOD + (size_t)(k0 + j) * NQKV + half * 32;
        #pragma unroll
        for (int i = 0; i < 8; i++) {
            float4 k4 = *(const float4*)&src[4 * i];
            uint32_t h0 = pk_bf16(k4.x, k4.y);
            uint32_t h1 = pk_bf16(k4.z, k4.w);
            int c = half * 16 + 2 * i;
            kh[j * 32 + swz(c, j)]     = h0;
            kh[j * 32 + swz(c + 1, j)] = h1;
            kl[j * 32 + swz(c, j)]     = pk_bf16(k4.x - bflo(h0), k4.y - bfhi(h0));
            kl[j * 32 + swz(c + 1, j)] = pk_bf16(k4.z - bflo(h1), k4.w - bfhi(h1));
        }
    }
    // V transposed: jp = tid&31 (j-pair), d0 = (tid>>5)<<4
    {
        const int jp = tid & 31;
        const int d0 = (tid >> 5) << 4;
        const float* r0 = base + 2 * DMOD + (size_t)(k0 + 2 * jp) * NQKV + d0;
        const float* r1 = r0 + NQKV;
        #pragma unroll
        for (int i4 = 0; i4 < 4; i4++) {
            float4 x = *(const float4*)&r0[4 * i4];
            float4 yv = *(const float4*)&r1[4 * i4];
            float xs[4] = {x.x, x.y, x.z, x.w};
            float ys[4] = {yv.x, yv.y, yv.z, yv.w};
            #pragma unroll
            for (int e = 0; e < 4; e++) {
                int d = d0 + 4 * i4 + e;
                uint32_t hi = pk_bf16(xs[e], ys[e]);
                vh[d * 32 + swz(jp, d)] = hi;
                vl[d * 32 + swz(jp, d)] = pk_bf16(xs[e] - bflo(hi), ys[e] - bfhi(hi));
            }
        }
    }
}

// ===========================================================================
// tf32 tensor-core GEMM + bias. Inputs PRE-ROUNDED to tf32 -> no cvt in loop.
// ===========================================================================
#define GSTAGES 4
#define GBK 16
#define A_ST_F (128 * 20)
#define B_ST_F (16 * 136)
#define ST_F   (A_ST_F + B_ST_F)
#define GEMM_SMEM (GSTAGES * ST_F * 4)

__global__ __launch_bounds__(256, 1)
void gemm_tc(const float* __restrict__ A, const float* __restrict__ W,
             const float* __restrict__ bias, float* __restrict__ C,
             int M, int N, int K)
{
    extern __shared__ __align__(16) float sm_f[];
    const uint32_t sm_b = smem_u32(sm_f);

    const int tid  = threadIdx.x;
    const int wid  = tid >> 5;
    const int lane = tid & 31;
    const int grp  = lane >> 2;
    const int qid  = lane & 3;
    const int wm   = wid >> 2;
    const int wn   = wid & 3;
    const int m0   = blockIdx.y * 128;
    const int n0   = blockIdx.x * 128;
    const int NCHUNK = K / GBK;

    float acc[4][4][4];
    #pragma unroll
    for (int mi = 0; mi < 4; mi++)
        #pragma unroll
        for (int ni = 0; ni < 4; ni++)
            #pragma unroll
            for (int q = 0; q < 4; q++) acc[mi][ni][q] = 0.0f;

    auto load_stage = [&](int s, int k0) {
        const uint32_t as = sm_b + s * (ST_F * 4);
        const uint32_t bs = as + A_ST_F * 4;
        #pragma unroll
        for (int i = 0; i < 2; i++) {
            int id  = tid + i * 256;
            int row = id >> 2;
            int ch  = id & 3;
            cp_async16(as + row * 80 + ch * 16,
                       A + (size_t)(m0 + row) * K + k0 + ch * 4);
        }
        #pragma unroll
        for (int i = 0; i < 2; i++) {
            int id  = tid + i * 256;
            int row = id >> 5;
            int ch  = id & 31;
            cp_async16(bs + row * 544 + ch * 16,
                       W + (size_t)(k0 + row) * N + n0 + ch * 4);
        }
        cp_commit();
    };

    #pragma unroll
    for (int s = 0; s < GSTAGES - 1; s++) load_stage(s, s * GBK);

    for (int c = 0; c < NCHUNK; c++) {
        CP_WAIT(GSTAGES - 2);
        __syncthreads();
        {
            int nc = c + GSTAGES - 1;
            if (nc < NCHUNK) load_stage(nc % GSTAGES, nc * GBK);
        }

        const float* as = sm_f + (c % GSTAGES) * ST_F;
        const float* bs = as + A_ST_F;

        #pragma unroll
        for (int ks = 0; ks < 2; ks++) {
            const int kc = ks * 8;
            uint32_t af[4][4], bf[4][2];
            #pragma unroll
            for (int mi = 0; mi < 4; mi++) {
                int r = wm * 64 + mi * 16 + grp;
                int cc = kc + qid;
                af[mi][0] = __float_as_uint(as[r * 20 + cc]);
                af[mi][1] = __float_as_uint(as[(r + 8) * 20 + cc]);
                af[mi][2] = __float_as_uint(as[r * 20 + cc + 4]);
                af[mi][3] = __float_as_uint(as[(r + 8) * 20 + cc + 4]);
            }
            #pragma unroll
            for (int ni = 0; ni < 4; ni++) {
                int n = wn * 32 + ni * 8 + grp;
                int kk = kc + qid;
                bf[ni][0] = __float_as_uint(bs[kk * 136 + n]);
                bf[ni][1] = __float_as_uint(bs[(kk + 4) * 136 + n]);
            }
            #pragma unroll
            for (int mi = 0; mi < 4; mi++)
                #pragma unroll
                for (int ni = 0; ni < 4; ni++)
                    mma_tf32(acc[mi][ni], af[mi], bf[ni]);
        }
        __syncthreads();
    }

    #pragma unroll
    for (int mi = 0; mi < 4; mi++) {
        int r0 = m0 + wm * 64 + mi * 16 + grp;
        #pragma unroll
        for (int ni = 0; ni < 4; ni++) {
            int col = n0 + wn * 32 + ni * 8 + qid * 2;
            float2 bv = *(const float2*)&bias[col];
            float2 o0, o1;
            o0.x = acc[mi][ni][0] + bv.x;  o0.y = acc[mi][ni][1] + bv.y;
            o1.x = acc[mi][ni][2] + bv.x;  o1.y = acc[mi][ni][3] + bv.y;
            *(float2*)&C[(size_t)r0 * N + col]       = o0;
            *(float2*)&C[(size_t)(r0 + 8) * N + col] = o1;
        }
    }
}

// ===========================================================================
// Flash-attention (causal), bf16 3-term mma.sync.
// Round-9: K/V pre-converted in gmem (swizzled bf16 hi/lo tiles); mainloop is
// double-buffered cp.async + MMAs only. smem = 2 stages x 32KB.
// Stage layout (words): [Khi 2048][Klo 2048][Vhi 2048][Vlo 2048]
// ===========================================================================
#define ATT_STAGE_W 8192
#define ATTN_SMEM (2 * ATT_STAGE_W * 4)   // 65536 B

__global__ __launch_bounds__(128, 3)
void attn_mma(const float* __restrict__ qkv,
              const uint32_t* __restrict__ kw, const uint32_t* __restrict__ vw,
              float* __restrict__ y)
{
    extern __shared__ __align__(16) uint32_t sm_w[];
    const uint32_t sm_b = smem_u32(sm_w);

    const int tid  = threadIdx.x;
    const int wid  = tid >> 5;
    const int lane = tid & 31;
    const int grp  = lane >> 2;
    const int qid  = lane & 3;

    const int qt = gridDim.x - 1 - blockIdx.x;
    const int bh = blockIdx.y;
    const int b  = bh >> 4;
    const int h  = bh & 15;
    const int q0 = qt * 64;

    const float* base = qkv + (size_t)(b * LSEQ) * NQKV + h * HDIM;
    const char* gk_base = (const char*)(kw + (size_t)bh * 32 * 2 * 2048);
    const char* gv_base = (const char*)(vw + (size_t)bh * 32 * 2 * 2048);

    // ---- Q fragments (hi/lo bf16) ----
    uint32_t qh[4][4], ql[4][4];
    const int i0 = q0 + wid * 16 + grp;
    #pragma unroll
    for (int kc = 0; kc < 4; kc++)
        #pragma unroll
        for (int hh = 0; hh < 2; hh++)
            #pragma unroll
            for (int rr = 0; rr < 2; rr++) {
                const float* p = base + (size_t)(i0 + 8 * rr) * NQKV
                               + kc * 16 + hh * 8 + 2 * qid;
                float2 v = *(const float2*)p;
                uint32_t hi = pk_bf16(v.x, v.y);
                qh[kc][2 * hh + rr] = hi;
                ql[kc][2 * hh + rr] = pk_bf16(v.x - bflo(hi), v.y - bfhi(hi));
            }

    float o[8][4];
    #pragma unroll
    for (int nt = 0; nt < 8; nt++)
        #pragma unroll
        for (int c = 0; c < 4; c++) o[nt][c] = 0.0f;
    float m0f = -1e30f, m1f = -1e30f, l0 = 0.0f, l1 = 0.0f;

    // prefetch tile kt into stage s: 32KB = 2048 16B-chunks, 16 per thread
    auto prefetch = [&](int kt, int s) {
        const char* gk = gk_base + (size_t)kt * 16384;
        const char* gv = gv_base + (size_t)kt * 16384;
        const uint32_t dst = sm_b + s * (ATT_STAGE_W * 4);
        #pragma unroll
        for (int i = 0; i < 16; i++) {
            int id = tid + i * 128;          // 0..2047
            const char* src = (id < 1024) ? (gk + id * 16)
                                          : (gv + (id - 1024) * 16);
            cp_async16(dst + id * 16, src);
        }
        cp_commit();
    };

    prefetch(0, 0);

    for (int kt = 0; kt <= qt; kt++) {
        const int k0 = kt * 64;
        const int s  = kt & 1;
        if (kt < qt) { prefetch(kt + 1, s ^ 1); CP_WAIT(1); }
        else         { CP_WAIT(0); }
        __syncthreads();

        const uint32_t* KhiW = sm_w + s * ATT_STAGE_W;
        const uint32_t* KloW = KhiW + 2048;
        const uint32_t* VhW  = KhiW + 4096;
        const uint32_t* VlW  = KhiW + 6144;

        // ---- S = Q @ K^T (3-term bf16) ----
        float sreg[8][4];
        #pragma unroll
        for (int nt = 0; nt < 8; nt++)
            #pragma unroll
            for (int c = 0; c < 4; c++) sreg[nt][c] = 0.0f;

        #pragma unroll
        for (int nt = 0; nt < 8; nt++) {
            const int j = nt * 8 + grp;
            const uint32_t* kh = KhiW + j * 32;
            const uint32_t* kl = KloW + j * 32;
            #pragma unroll
            for (int kc = 0; kc < 4; kc++) {
                uint32_t b0h = kh[swz(8 * kc + qid, j)];
                uint32_t b1h = kh[swz(8 * kc + 4 + qid, j)];
                uint32_t b0l = kl[swz(8 * kc + qid, j)];
                uint32_t b1l = kl[swz(8 * kc + 4 + qid, j)];
                mma_bf16(sreg[nt], qh[kc], b0h, b1h);
                mma_bf16(sreg[nt], qh[kc], b0l, b1l);
                mma_bf16(sreg[nt], ql[kc], b0h, b1h);
            }
        }

        // ---- scale + causal mask ----
        const float scale = 0.125f;
        if (kt == qt) {
            #pragma unroll
            for (int nt = 0; nt < 8; nt++)
                #pragma unroll
                for (int c = 0; c < 4; c++) {
                    int j = k0 + nt * 8 + 2 * qid + (c & 1);
                    int i = (c < 2) ? i0 : (i0 + 8);
                    float sv = sreg[nt][c] * scale;
                    if (j > i) sv = -1e30f;
                    sreg[nt][c] = sv;
                }
        } else {
            #pragma unroll
            for (int nt = 0; nt < 8; nt++)
                #pragma unroll
                for (int c = 0; c < 4; c++) sreg[nt][c] *= scale;
        }

        // ---- online softmax: row max ----
        float mx0 = -1e30f, mx1 = -1e30f;
        #pragma unroll
        for (int nt = 0; nt < 8; nt++) {
            mx0 = fmaxf(mx0, fmaxf(sreg[nt][0], sreg[nt][1]));
            mx1 = fmaxf(mx1, fmaxf(sreg[nt][2], sreg[nt][3]));
        }
        #pragma unroll
        for (int off = 1; off <= 2; off <<= 1) {
            mx0 = fmaxf(mx0, __shfl_xor_sync(0xffffffffu, mx0, off));
            mx1 = fmaxf(mx1, __shfl_xor_sync(0xffffffffu, mx1, off));
        }
        float mn0 = fmaxf(m0f, mx0);
        float mn1 = fmaxf(m1f, mx1);
        float a0 = __expf(m0f - mn0);
        float a1 = __expf(m1f - mn1);
        m0f = mn0; m1f = mn1;
        #pragma unroll
        for (int nt = 0; nt < 8; nt++) {
            o[nt][0] *= a0;  o[nt][1] *= a0;
            o[nt][2] *= a1;  o[nt][3] *= a1;
        }

        // ---- exp, repack, PV mma (3-term) ----
        float rs0 = 0.0f, rs1 = 0.0f;
        #pragma unroll
        for (int kc2 = 0; kc2 < 4; kc2++) {
            uint32_t ph[4], pl[4];
            #pragma unroll
            for (int part = 0; part < 2; part++) {
                const int nt = kc2 * 2 + part;
                float p0 = __expf(sreg[nt][0] - mn0);
                float p1 = __expf(sreg[nt][1] - mn0);
                float p2 = __expf(sreg[nt][2] - mn1);
                float p3 = __expf(sreg[nt][3] - mn1);
                rs0 += p0 + p1;
                rs1 += p2 + p3;
                uint32_t u01 = pk_bf16(p0, p1);
                uint32_t u23 = pk_bf16(p2, p3);
                ph[2 * part]     = u01;
                ph[2 * part + 1] = u23;
                pl[2 * part]     = pk_bf16(p0 - bflo(u01), p1 - bfhi(u01));
                pl[2 * part + 1] = pk_bf16(p2 - bflo(u23), p3 - bfhi(u23));
            }
            #pragma unroll
            for (int ont = 0; ont < 8; ont++) {
                const int d = ont * 8 + grp;
                const uint32_t* vh = VhW + d * 32;
                const uint32_t* vl = VlW + d * 32;
                uint32_t b0h = vh[swz(8 * kc2 + qid, d)];
                uint32_t b1h = vh[swz(8 * kc2 + 4 + qid, d)];
                uint32_t b0l = vl[swz(8 * kc2 + qid, d)];
                uint32_t b1l = vl[swz(8 * kc2 + 4 + qid, d)];
                mma_bf16(o[ont], ph, b0h, b1h);
                mma_bf16(o[ont], ph, b0l, b1l);
                mma_bf16(o[ont], pl, b0h, b1h);
            }
        }
        #pragma unroll
        for (int off = 1; off <= 2; off <<= 1) {
            rs0 += __shfl_xor_sync(0xffffffffu, rs0, off);
            rs1 += __shfl_xor_sync(0xffffffffu, rs1, off);
        }
        l0 = l0 * a0 + rs0;
        l1 = l1 * a1 + rs1;

        __syncthreads();   // all warps done with stage s before it is refilled
    }

    // ---- epilogue: tf32-rounded store (feeds pre-rounded proj GEMM) ----
    const float inv0 = 1.0f / l0;
    const float inv1 = 1.0f / l1;
    #pragma unroll
    for (int ont = 0; ont < 8; ont++) {
        int col = h * HDIM + ont * 8 + 2 * qid;
        float2 v0, v1;
        v0.x = __uint_as_float(f2tf32(o[ont][0] * inv0));
        v0.y = __uint_as_float(f2tf32(o[ont][1] * inv0));
        v1.x = __uint_as_float(f2tf32(o[ont][2] * inv1));
        v1.y = __uint_as_float(f2tf32(o[ont][3] * inv1));
        *(float2*)&y[(size_t)(b * LSEQ + i0) * DMOD + col]     = v0;
        *(float2*)&y[(size_t)(b * LSEQ + i0 + 8) * DMOD + col] = v1;
    }
}

// ===========================================================================
// Launch
// ===========================================================================
extern "C" void kernel_launch(void* const* d_in, const int* in_sizes, int n_in,
                              void* d_out, int out_size)
{
    (void)in_sizes; (void)n_in; (void)out_size;
    const float* x     = (const float*)d_in[0];
    const float* Wqkv  = (const float*)d_in[1];
    const float* bqkv  = (const float*)d_in[2];
    const float* Wproj = (const float*)d_in[3];
    const float* bproj = (const float*)d_in[4];
    float* out = (float*)d_out;

    float *qkvp, *yp, *xr, *wqkvr, *wprojr;
    uint32_t *kwp, *vwp;
    cudaGetSymbolAddress((void**)&qkvp, g_qkv);
    cudaGetSymbolAddress((void**)&yp, g_y);
    cudaGetSymbolAddress((void**)&xr, g_xr);
    cudaGetSymbolAddress((void**)&wqkvr, g_wqkvr);
    cudaGetSymbolAddress((void**)&wprojr, g_wprojr);
    cudaGetSymbolAddress((void**)&kwp, g_kw);
    cudaGetSymbolAddress((void**)&vwp, g_vw);

    static bool attr_set = false;
    if (!attr_set) {
        cudaFuncSetAttribute(gemm_tc, cudaFuncAttributeMaxDynamicSharedMemorySize,
                             GEMM_SMEM);
        cudaFuncSetAttribute(attn_mma, cudaFuncAttributeMaxDynamicSharedMemorySize,
                             ATTN_SMEM);
        attr_set = true;
    }

    // Pre-round inputs to tf32 (rna), once
    {
        int n4x = MROWS * DMOD / 4;
        int n4q = DMOD * NQKV / 4;
        int n4p = DMOD * DMOD / 4;
        round_tf32_kernel<<<(n4x + 255) / 256, 256>>>(x, xr, n4x);
        round_tf32_kernel<<<(n4q + 255) / 256, 256>>>(Wqkv, wqkvr, n4q);
        round_tf32_kernel<<<(n4p + 255) / 256, 256>>>(Wproj, wprojr, n4p);
    }

    // QKV projection
    gemm_tc<<<dim3(NQKV / 128, MROWS / 128), 256, GEMM_SMEM>>>(
        xr, wqkvr, bqkv, qkvp, MROWS, NQKV, DMOD);
    // K/V -> swizzled bf16 hi/lo tiles
    kvconv_kernel<<<dim3(32, 64), 128>>>(qkvp, kwp, vwp);
    // Causal flash attention
    attn_mma<<<dim3(LSEQ / 64, BSZ * NHEAD), 128, ATTN_SMEM>>>(qkvp, kwp, vwp, yp);
    // Output projection (y already tf32-rounded by attn epilogue)
    gemm_tc<<<dim3(DMOD / 128, MROWS / 128), 256, GEMM_SMEM>>>(
        yp, wprojr, bproj, out, MROWS, DMOD, DMOD);
}

// round 11
// speedup vs baseline: 3.2475x; 1.1311x over previous
#include <cuda_runtime.h>
#include <cuda_bf16.h>
#include <math.h>
#include <stdint.h>

// Problem constants
#define BSZ   4
#define LSEQ  2048
#define DMOD  1024
#define NHEAD 16
#define HDIM  64
#define MROWS (BSZ * LSEQ)      // 8192
#define NQKV  (3 * DMOD)        // 3072

// Scratch (allocation-free rule: device globals)
__device__ __align__(16) float g_qkv[(size_t)MROWS * NQKV];   // [B*L, 3D]
__device__ __align__(16) float g_y[(size_t)MROWS * DMOD];     // attn out (tf32-rounded)
__device__ __align__(16) float g_xr[(size_t)MROWS * DMOD];        // x, tf32-rounded
__device__ __align__(16) float g_wqkvr[(size_t)DMOD * NQKV];      // Wqkv, rounded
__device__ __align__(16) float g_wprojr[(size_t)DMOD * DMOD];     // Wproj, rounded
// Pre-converted KV: per (bh, jtile): [Khi 2048w][Klo 2048w], swizzled tiles
__device__ __align__(16) uint32_t g_kw[(size_t)64 * 32 * 2 * 2048];
__device__ __align__(16) uint32_t g_vw[(size_t)64 * 32 * 2 * 2048];

// ===========================================================================
// Helpers
// ===========================================================================
__device__ __forceinline__ uint32_t smem_u32(const void* p) {
    uint32_t a;
    asm("{ .reg .u64 t; cvta.to.shared.u64 t, %1; cvt.u32.u64 %0, t; }"
        : "=r"(a) : "l"(p));
    return a;
}
__device__ __forceinline__ void cp_async16(uint32_t dst, const void* src) {
    asm volatile("cp.async.cg.shared.global [%0], [%1], 16;"
                 :: "r"(dst), "l"(src) : "memory");
}
__device__ __forceinline__ void cp_commit() {
    asm volatile("cp.async.commit_group;" ::: "memory");
}
#define CP_WAIT(n) asm volatile("cp.async.wait_group %0;" :: "n"(n) : "memory")

__device__ __forceinline__ uint32_t f2tf32(float f) {
    uint32_t r;
    asm("cvt.rna.tf32.f32 %0, %1;" : "=r"(r) : "f"(f));
    return r;
}
__device__ __forceinline__ void mma_tf32(float* c, const uint32_t* a, const uint32_t* b) {
    asm volatile(
        "mma.sync.aligned.m16n8k8.row.col.f32.tf32.tf32.f32 "
        "{%0,%1,%2,%3}, {%4,%5,%6,%7}, {%8,%9}, {%0,%1,%2,%3};\n"
        : "+f"(c[0]), "+f"(c[1]), "+f"(c[2]), "+f"(c[3])
        : "r"(a[0]), "r"(a[1]), "r"(a[2]), "r"(a[3]), "r"(b[0]), "r"(b[1]));
}
__device__ __forceinline__ uint32_t pk_bf16(float x, float y) {
    uint32_t r;
    asm("cvt.rn.bf16x2.f32 %0, %1, %2;" : "=r"(r) : "f"(y), "f"(x));
    return r;
}
__device__ __forceinline__ float bflo(uint32_t u) { return __uint_as_float(u << 16); }
__device__ __forceinline__ float bfhi(uint32_t u) { return __uint_as_float(u & 0xffff0000u); }

__device__ __forceinline__ void mma_bf16(float* c, const uint32_t* a,
                                         uint32_t b0, uint32_t b1) {
    asm volatile(
        "mma.sync.aligned.m16n8k16.row.col.f32.bf16.bf16.f32 "
        "{%0,%1,%2,%3}, {%4,%5,%6,%7}, {%8,%9}, {%0,%1,%2,%3};\n"
        : "+f"(c[0]), "+f"(c[1]), "+f"(c[2]), "+f"(c[3])
        : "r"(a[0]), "r"(a[1]), "r"(a[2]), "r"(a[3]), "r"(b0), "r"(b1));
}
__device__ __forceinline__ int swz(int col, int row) {
    return col ^ (((row & 7) << 2) | ((row >> 3) & 3));
}

// ===========================================================================
// Pre-pass 1: elementwise tf32(rna) rounding
// ===========================================================================
__global__ void round_tf32_kernel(const float* __restrict__ in,
                                  float* __restrict__ out, int n4)
{
    int i = blockIdx.x * blockDim.x + threadIdx.x;
    if (i < n4) {
        float4 v = ((const float4*)in)[i];
        v.x = __uint_as_float(f2tf32(v.x));
        v.y = __uint_as_float(f2tf32(v.y));
        v.z = __uint_as_float(f2tf32(v.z));
        v.w = __uint_as_float(f2tf32(v.w));
        ((float4*)out)[i] = v;
    }
}

// ===========================================================================
// Pre-pass 2: K/V fp32 -> swizzled bf16 hi/lo gmem tiles
// ===========================================================================
__global__ __launch_bounds__(128)
void kvconv_kernel(const float* __restrict__ qkv,
                   uint32_t* __restrict__ kw, uint32_t* __restrict__ vw)
{
    const int tid = threadIdx.x;
    const int jt  = blockIdx.x;
    const int bh  = blockIdx.y;
    const int b   = bh >> 4;
    const int h   = bh & 15;
    const int k0  = jt * 64;
    const float* base = qkv + (size_t)(b * LSEQ) * NQKV + h * HDIM;

    uint32_t* kh = kw + ((size_t)(bh * 32 + jt) * 2) * 2048;
    uint32_t* kl = kh + 2048;
    uint32_t* vh = vw + ((size_t)(bh * 32 + jt) * 2) * 2048;
    uint32_t* vl = vh + 2048;

    {
        const int j    = tid & 63;
        const int half = tid >> 6;
        const float* src = base + DMOD + (size_t)(k0 + j) * NQKV + half * 32;
        #pragma unroll
        for (int i = 0; i < 8; i++) {
            float4 k4 = *(const float4*)&src[4 * i];
            uint32_t h0 = pk_bf16(k4.x, k4.y);
            uint32_t h1 = pk_bf16(k4.z, k4.w);
            int c = half * 16 + 2 * i;
            kh[j * 32 + swz(c, j)]     = h0;
            kh[j * 32 + swz(c + 1, j)] = h1;
            kl[j * 32 + swz(c, j)]     = pk_bf16(k4.x - bflo(h0), k4.y - bfhi(h0));
            kl[j * 32 + swz(c + 1, j)] = pk_bf16(k4.z - bflo(h1), k4.w - bfhi(h1));
        }
    }
    {
        const int jp = tid & 31;
        const int d0 = (tid >> 5) << 4;
        const float* r0 = base + 2 * DMOD + (size_t)(k0 + 2 * jp) * NQKV + d0;
        const float* r1 = r0 + NQKV;
        #pragma unroll
        for (int i4 = 0; i4 < 4; i4++) {
            float4 x = *(const float4*)&r0[4 * i4];
            float4 yv = *(const float4*)&r1[4 * i4];
            float xs[4] = {x.x, x.y, x.z, x.w};
            float ys[4] = {yv.x, yv.y, yv.z, yv.w};
            #pragma unroll
            for (int e = 0; e < 4; e++) {
                int d = d0 + 4 * i4 + e;
                uint32_t hi = pk_bf16(xs[e], ys[e]);
                vh[d * 32 + swz(jp, d)] = hi;
                vl[d * 32 + swz(jp, d)] = pk_bf16(xs[e] - bflo(hi), ys[e] - bfhi(hi));
            }
        }
    }
}

// ===========================================================================
// tf32 tensor-core GEMM + bias. Inputs PRE-ROUNDED to tf32 -> no cvt in loop.
// __launch_bounds__(256, 2) clamps regs to 128 so 2 CTAs/SM fit
// (round-9 crept to 143 regs -> 1 CTA/SM -> tensor util regression).
// ===========================================================================
#define GSTAGES 4
#define GBK 16
#define A_ST_F (128 * 20)
#define B_ST_F (16 * 136)
#define ST_F   (A_ST_F + B_ST_F)
#define GEMM_SMEM (GSTAGES * ST_F * 4)

__global__ __launch_bounds__(256, 2)
void gemm_tc(const float* __restrict__ A, const float* __restrict__ W,
             const float* __restrict__ bias, float* __restrict__ C,
             int M, int N, int K)
{
    extern __shared__ __align__(16) float sm_f[];
    const uint32_t sm_b = smem_u32(sm_f);

    const int tid  = threadIdx.x;
    const int wid  = tid >> 5;
    const int lane = tid & 31;
    const int grp  = lane >> 2;
    const int qid  = lane & 3;
    const int wm   = wid >> 2;
    const int wn   = wid & 3;
    const int m0   = blockIdx.y * 128;
    const int n0   = blockIdx.x * 128;
    const int NCHUNK = K / GBK;

    float acc[4][4][4];
    #pragma unroll
    for (int mi = 0; mi < 4; mi++)
        #pragma unroll
        for (int ni = 0; ni < 4; ni++)
            #pragma unroll
            for (int q = 0; q < 4; q++) acc[mi][ni][q] = 0.0f;

    auto load_stage = [&](int s, int k0) {
        const uint32_t as = sm_b + s * (ST_F * 4);
        const uint32_t bs = as + A_ST_F * 4;
        #pragma unroll
        for (int i = 0; i < 2; i++) {
            int id  = tid + i * 256;
            int row = id >> 2;
            int ch  = id & 3;
            cp_async16(as + row * 80 + ch * 16,
                       A + (size_t)(m0 + row) * K + k0 + ch * 4);
        }
        #pragma unroll
        for (int i = 0; i < 2; i++) {
            int id  = tid + i * 256;
            int row = id >> 5;
            int ch  = id & 31;
            cp_async16(bs + row * 544 + ch * 16,
                       W + (size_t)(k0 + row) * N + n0 + ch * 4);
        }
        cp_commit();
    };

    #pragma unroll
    for (int s = 0; s < GSTAGES - 1; s++) load_stage(s, s * GBK);

    for (int c = 0; c < NCHUNK; c++) {
        CP_WAIT(GSTAGES - 2);
        __syncthreads();
        {
            int nc = c + GSTAGES - 1;
            if (nc < NCHUNK) load_stage(nc % GSTAGES, nc * GBK);
        }

        const float* as = sm_f + (c % GSTAGES) * ST_F;
        const float* bs = as + A_ST_F;

        #pragma unroll
        for (int ks = 0; ks < 2; ks++) {
            const int kc = ks * 8;
            uint32_t af[4][4], bf[4][2];
            #pragma unroll
            for (int mi = 0; mi < 4; mi++) {
                int r = wm * 64 + mi * 16 + grp;
                int cc = kc + qid;
                af[mi][0] = __float_as_uint(as[r * 20 + cc]);
                af[mi][1] = __float_as_uint(as[(r + 8) * 20 + cc]);
                af[mi][2] = __float_as_uint(as[r * 20 + cc + 4]);
                af[mi][3] = __float_as_uint(as[(r + 8) * 20 + cc + 4]);
            }
            #pragma unroll
            for (int ni = 0; ni < 4; ni++) {
                int n = wn * 32 + ni * 8 + grp;
                int kk = kc + qid;
                bf[ni][0] = __float_as_uint(bs[kk * 136 + n]);
                bf[ni][1] = __float_as_uint(bs[(kk + 4) * 136 + n]);
            }
            #pragma unroll
            for (int mi = 0; mi < 4; mi++)
                #pragma unroll
                for (int ni = 0; ni < 4; ni++)
                    mma_tf32(acc[mi][ni], af[mi], bf[ni]);
        }
        __syncthreads();
    }

    #pragma unroll
    for (int mi = 0; mi < 4; mi++) {
        int r0 = m0 + wm * 64 + mi * 16 + grp;
        #pragma unroll
        for (int ni = 0; ni < 4; ni++) {
            int col = n0 + wn * 32 + ni * 8 + qid * 2;
            float2 bv = *(const float2*)&bias[col];
            float2 o0, o1;
            o0.x = acc[mi][ni][0] + bv.x;  o0.y = acc[mi][ni][1] + bv.y;
            o1.x = acc[mi][ni][2] + bv.x;  o1.y = acc[mi][ni][3] + bv.y;
            *(float2*)&C[(size_t)r0 * N + col]       = o0;
            *(float2*)&C[(size_t)(r0 + 8) * N + col] = o1;
        }
    }
}

// ===========================================================================
// Flash-attention (causal), bf16 3-term mma.sync; K/V pre-converted in gmem.
// Double-buffered cp.async mainloop. smem = 2 stages x 32KB.
// ===========================================================================
#define ATT_STAGE_W 8192
#define ATTN_SMEM (2 * ATT_STAGE_W * 4)   // 65536 B

__global__ __launch_bounds__(128, 3)
void attn_mma(const float* __restrict__ qkv,
              const uint32_t* __restrict__ kw, const uint32_t* __restrict__ vw,
              float* __restrict__ y)
{
    extern __shared__ __align__(16) uint32_t sm_w[];
    const uint32_t sm_b = smem_u32(sm_w);

    const int tid  = threadIdx.x;
    const int wid  = tid >> 5;
    const int lane = tid & 31;
    const int grp  = lane >> 2;
    const int qid  = lane & 3;

    const int qt = gridDim.x - 1 - blockIdx.x;
    const int bh = blockIdx.y;
    const int b  = bh >> 4;
    const int h  = bh & 15;
    const int q0 = qt * 64;

    const float* base = qkv + (size_t)(b * LSEQ) * NQKV + h * HDIM;
    const char* gk_base = (const char*)(kw + (size_t)bh * 32 * 2 * 2048);
    const char* gv_base = (const char*)(vw + (size_t)bh * 32 * 2 * 2048);

    // ---- Q fragments (hi/lo bf16) ----
    uint32_t qh[4][4], ql[4][4];
    const int i0 = q0 + wid * 16 + grp;
    #pragma unroll
    for (int kc = 0; kc < 4; kc++)
        #pragma unroll
        for (int hh = 0; hh < 2; hh++)
            #pragma unroll
            for (int rr = 0; rr < 2; rr++) {
                const float* p = base + (size_t)(i0 + 8 * rr) * NQKV
                               + kc * 16 + hh * 8 + 2 * qid;
                float2 v = *(const float2*)p;
                uint32_t hi = pk_bf16(v.x, v.y);
                qh[kc][2 * hh + rr] = hi;
                ql[kc][2 * hh + rr] = pk_bf16(v.x - bflo(hi), v.y - bfhi(hi));
            }

    float o[8][4];
    #pragma unroll
    for (int nt = 0; nt < 8; nt++)
        #pragma unroll
        for (int c = 0; c < 4; c++) o[nt][c] = 0.0f;
    float m0f = -1e30f, m1f = -1e30f, l0 = 0.0f, l1 = 0.0f;

    auto prefetch = [&](int kt, int s) {
        const char* gk = gk_base + (size_t)kt * 16384;
        const char* gv = gv_base + (size_t)kt * 16384;
        const uint32_t dst = sm_b + s * (ATT_STAGE_W * 4);
        #pragma unroll
        for (int i = 0; i < 16; i++) {
            int id = tid + i * 128;          // 0..2047
            const char* src = (id < 1024) ? (gk + id * 16)
                                          : (gv + (id - 1024) * 16);
            cp_async16(dst + id * 16, src);
        }
        cp_commit();
    };

    prefetch(0, 0);

    for (int kt = 0; kt <= qt; kt++) {
        const int k0 = kt * 64;
        const int s  = kt & 1;
        if (kt < qt) { prefetch(kt + 1, s ^ 1); CP_WAIT(1); }
        else         { CP_WAIT(0); }
        __syncthreads();

        const uint32_t* KhiW = sm_w + s * ATT_STAGE_W;
        const uint32_t* KloW = KhiW + 2048;
        const uint32_t* VhW  = KhiW + 4096;
        const uint32_t* VlW  = KhiW + 6144;

        // ---- S = Q @ K^T (3-term bf16) ----
        float sreg[8][4];
        #pragma unroll
        for (int nt = 0; nt < 8; nt++)
            #pragma unroll
            for (int c = 0; c < 4; c++) sreg[nt][c] = 0.0f;

        #pragma unroll
        for (int nt = 0; nt < 8; nt++) {
            const int j = nt * 8 + grp;
            const uint32_t* kh = KhiW + j * 32;
            const uint32_t* kl = KloW + j * 32;
            #pragma unroll
            for (int kc = 0; kc < 4; kc++) {
                uint32_t b0h = kh[swz(8 * kc + qid, j)];
                uint32_t b1h = kh[swz(8 * kc + 4 + qid, j)];
                uint32_t b0l = kl[swz(8 * kc + qid, j)];
                uint32_t b1l = kl[swz(8 * kc + 4 + qid, j)];
                mma_bf16(sreg[nt], qh[kc], b0h, b1h);
                mma_bf16(sreg[nt], qh[kc], b0l, b1l);
                mma_bf16(sreg[nt], ql[kc], b0h, b1h);
            }
        }

        // ---- scale + causal mask ----
        const float scale = 0.125f;
        if (kt == qt) {
            #pragma unroll
            for (int nt = 0; nt < 8; nt++)
                #pragma unroll
                for (int c = 0; c < 4; c++) {
                    int j = k0 + nt * 8 + 2 * qid + (c & 1);
                    int i = (c < 2) ? i0 : (i0 + 8);
                    float sv = sreg[nt][c] * scale;
                    if (j > i) sv = -1e30f;
                    sreg[nt][c] = sv;
                }
        } else {
            #pragma unroll
            for (int nt = 0; nt < 8; nt++)
                #pragma unroll
                for (int c = 0; c < 4; c++) sreg[nt][c] *= scale;
        }

        // ---- online softmax ----
        float mx0 = -1e30f, mx1 = -1e30f;
        #pragma unroll
        for (int nt = 0; nt < 8; nt++) {
            mx0 = fmaxf(mx0, fmaxf(sreg[nt][0], sreg[nt][1]));
            mx1 = fmaxf(mx1, fmaxf(sreg[nt][2], sreg[nt][3]));
        }
        #pragma unroll
        for (int off = 1; off <= 2; off <<= 1) {
            mx0 = fmaxf(mx0, __shfl_xor_sync(0xffffffffu, mx0, off));
            mx1 = fmaxf(mx1, __shfl_xor_sync(0xffffffffu, mx1, off));
        }
        float mn0 = fmaxf(m0f, mx0);
        float mn1 = fmaxf(m1f, mx1);
        float a0 = __expf(m0f - mn0);
        float a1 = __expf(m1f - mn1);
        m0f = mn0; m1f = mn1;
        #pragma unroll
        for (int nt = 0; nt < 8; nt++) {
            o[nt][0] *= a0;  o[nt][1] *= a0;
            o[nt][2] *= a1;  o[nt][3] *= a1;
        }

        // ---- exp, repack, PV mma (3-term) ----
        float rs0 = 0.0f, rs1 = 0.0f;
        #pragma unroll
        for (int kc2 = 0; kc2 < 4; kc2++) {
            uint32_t ph[4], pl[4];
            #pragma unroll
            for (int part = 0; part < 2; part++) {
                const int nt = kc2 * 2 + part;
                float p0 = __expf(sreg[nt][0] - mn0);
                float p1 = __expf(sreg[nt][1] - mn0);
                float p2 = __expf(sreg[nt][2] - mn1);
                float p3 = __expf(sreg[nt][3] - mn1);
                rs0 += p0 + p1;
                rs1 += p2 + p3;
                uint32_t u01 = pk_bf16(p0, p1);
                uint32_t u23 = pk_bf16(p2, p3);
                ph[2 * part]     = u01;
                ph[2 * part + 1] = u23;
                pl[2 * part]     = pk_bf16(p0 - bflo(u01), p1 - bfhi(u01));
                pl[2 * part + 1] = pk_bf16(p2 - bflo(u23), p3 - bfhi(u23));
            }
            #pragma unroll
            for (int ont = 0; ont < 8; ont++) {
                const int d = ont * 8 + grp;
                const uint32_t* vh = VhW + d * 32;
                const uint32_t* vl = VlW + d * 32;
                uint32_t b0h = vh[swz(8 * kc2 + qid, d)];
                uint32_t b1h = vh[swz(8 * kc2 + 4 + qid, d)];
                uint32_t b0l = vl[swz(8 * kc2 + qid, d)];
                uint32_t b1l = vl[swz(8 * kc2 + 4 + qid, d)];
                mma_bf16(o[ont], ph, b0h, b1h);
                mma_bf16(o[ont], ph, b0l, b1l);
                mma_bf16(o[ont], pl, b0h, b1h);
            }
        }
        #pragma unroll
        for (int off = 1; off <= 2; off <<= 1) {
            rs0 += __shfl_xor_sync(0xffffffffu, rs0, off);
            rs1 += __shfl_xor_sync(0xffffffffu, rs1, off);
        }
        l0 = l0 * a0 + rs0;
        l1 = l1 * a1 + rs1;

        __syncthreads();
    }

    // ---- epilogue: tf32-rounded store (feeds pre-rounded proj GEMM) ----
    const float inv0 = 1.0f / l0;
    const float inv1 = 1.0f / l1;
    #pragma unroll
    for (int ont = 0; ont < 8; ont++) {
        int col = h * HDIM + ont * 8 + 2 * qid;
        float2 v0, v1;
        v0.x = __uint_as_float(f2tf32(o[ont][0] * inv0));
        v0.y = __uint_as_float(f2tf32(o[ont][1] * inv0));
        v1.x = __uint_as_float(f2tf32(o[ont][2] * inv1));
        v1.y = __uint_as_float(f2tf32(o[ont][3] * inv1));
        *(float2*)&y[(size_t)(b * LSEQ + i0) * DMOD + col]     = v0;
        *(float2*)&y[(size_t)(b * LSEQ + i0 + 8) * DMOD + col] = v1;
    }
}

// ===========================================================================
// Launch
// ===========================================================================
extern "C" void kernel_launch(void* const* d_in, const int* in_sizes, int n_in,
                              void* d_out, int out_size)
{
    (void)in_sizes; (void)n_in; (void)out_size;
    const float* x     = (const float*)d_in[0];
    const float* Wqkv  = (const float*)d_in[1];
    const float* bqkv  = (const float*)d_in[2];
    const float* Wproj = (const float*)d_in[3];
    const float* bproj = (const float*)d_in[4];
    float* out = (float*)d_out;

    float *qkvp, *yp, *xr, *wqkvr, *wprojr;
    uint32_t *kwp, *vwp;
    cudaGetSymbolAddress((void**)&qkvp, g_qkv);
    cudaGetSymbolAddress((void**)&yp, g_y);
    cudaGetSymbolAddress((void**)&xr, g_xr);
    cudaGetSymbolAddress((void**)&wqkvr, g_wqkvr);
    cudaGetSymbolAddress((void**)&wprojr, g_wprojr);
    cudaGetSymbolAddress((void**)&kwp, g_kw);
    cudaGetSymbolAddress((void**)&vwp, g_vw);

    static bool attr_set = false;
    if (!attr_set) {
        cudaFuncSetAttribute(gemm_tc, cudaFuncAttributeMaxDynamicSharedMemorySize,
                             GEMM_SMEM);
        cudaFuncSetAttribute(attn_mma, cudaFuncAttributeMaxDynamicSharedMemorySize,
                             ATTN_SMEM);
        attr_set = true;
    }

    // Pre-round inputs to tf32 (rna), once
    {
        int n4x = MROWS * DMOD / 4;
        int n4q = DMOD * NQKV / 4;
        int n4p = DMOD * DMOD / 4;
        round_tf32_kernel<<<(n4x + 255) / 256, 256>>>(x, xr, n4x);
        round_tf32_kernel<<<(n4q + 255) / 256, 256>>>(Wqkv, wqkvr, n4q);
        round_tf32_kernel<<<(n4p + 255) / 256, 256>>>(Wproj, wprojr, n4p);
    }

    // QKV projection
    gemm_tc<<<dim3(NQKV / 128, MROWS / 128), 256, GEMM_SMEM>>>(
        xr, wqkvr, bqkv, qkvp, MROWS, NQKV, DMOD);
    // K/V -> swizzled bf16 hi/lo tiles
    kvconv_kernel<<<dim3(32, 64), 128>>>(qkvp, kwp, vwp);
    // Causal flash attention
    attn_mma<<<dim3(LSEQ / 64, BSZ * NHEAD), 128, ATTN_SMEM>>>(qkvp, kwp, vwp, yp);
    // Output projection (y already tf32-rounded by attn epilogue)
    gemm_tc<<<dim3(DMOD / 128, MROWS / 128), 256, GEMM_SMEM>>>(
        yp, wprojr, bproj, out, MROWS, DMOD, DMOD);
}

// round 12
// speedup vs baseline: 3.6952x; 1.1379x over previous
#include <cuda_runtime.h>
#include <cuda_bf16.h>
#include <math.h>
#include <stdint.h>

// Problem constants
#define BSZ   4
#define LSEQ  2048
#define DMOD  1024
#define NHEAD 16
#define HDIM  64
#define MROWS (BSZ * LSEQ)      // 8192
#define NQKV  (3 * DMOD)        // 3072

// Scratch (allocation-free rule: device globals)
__device__ __align__(16) float g_qkv[(size_t)MROWS * NQKV];   // [B*L, 3D] row-major
__device__ __align__(16) float g_y[(size_t)MROWS * DMOD];     // attn out, FRAG-A layout
__device__ __align__(16) float g_xr[(size_t)MROWS * DMOD];    // x rounded, FRAG-A layout
__device__ __align__(16) float g_wqkvr[(size_t)DMOD * NQKV];  // Wqkv rounded, FRAG-B
__device__ __align__(16) float g_wprojr[(size_t)DMOD * DMOD]; // Wproj rounded, FRAG-B
// Pre-converted KV: per (bh, jtile): [Khi 2048w][Klo 2048w], swizzled tiles
__device__ __align__(16) uint32_t g_kw[(size_t)64 * 32 * 2 * 2048];
__device__ __align__(16) uint32_t g_vw[(size_t)64 * 32 * 2 * 2048];

// ===========================================================================
// Helpers
// ===========================================================================
__device__ __forceinline__ uint32_t smem_u32(const void* p) {
    uint32_t a;
    asm("{ .reg .u64 t; cvta.to.shared.u64 t, %1; cvt.u32.u64 %0, t; }"
        : "=r"(a) : "l"(p));
    return a;
}
__device__ __forceinline__ void cp_async16(uint32_t dst, const void* src) {
    asm volatile("cp.async.cg.shared.global [%0], [%1], 16;"
                 :: "r"(dst), "l"(src) : "memory");
}
__device__ __forceinline__ void cp_commit() {
    asm volatile("cp.async.commit_group;" ::: "memory");
}
#define CP_WAIT(n) asm volatile("cp.async.wait_group %0;" :: "n"(n) : "memory")

__device__ __forceinline__ uint32_t f2tf32(float f) {
    uint32_t r;
    asm("cvt.rna.tf32.f32 %0, %1;" : "=r"(r) : "f"(f));
    return r;
}
__device__ __forceinline__ void mma_tf32(float* c, const uint32_t* a, const uint32_t* b) {
    asm volatile(
        "mma.sync.aligned.m16n8k8.row.col.f32.tf32.tf32.f32 "
        "{%0,%1,%2,%3}, {%4,%5,%6,%7}, {%8,%9}, {%0,%1,%2,%3};\n"
        : "+f"(c[0]), "+f"(c[1]), "+f"(c[2]), "+f"(c[3])
        : "r"(a[0]), "r"(a[1]), "r"(a[2]), "r"(a[3]), "r"(b[0]), "r"(b[1]));
}
__device__ __forceinline__ uint32_t pk_bf16(float x, float y) {
    uint32_t r;
    asm("cvt.rn.bf16x2.f32 %0, %1, %2;" : "=r"(r) : "f"(y), "f"(x));
    return r;
}
__device__ __forceinline__ float bflo(uint32_t u) { return __uint_as_float(u << 16); }
__device__ __forceinline__ float bfhi(uint32_t u) { return __uint_as_float(u & 0xffff0000u); }

__device__ __forceinline__ void mma_bf16(float* c, const uint32_t* a,
                                         uint32_t b0, uint32_t b1) {
    asm volatile(
        "mma.sync.aligned.m16n8k16.row.col.f32.bf16.bf16.f32 "
        "{%0,%1,%2,%3}, {%4,%5,%6,%7}, {%8,%9}, {%0,%1,%2,%3};\n"
        : "+f"(c[0]), "+f"(c[1]), "+f"(c[2]), "+f"(c[3])
        : "r"(a[0]), "r"(a[1]), "r"(a[2]), "r"(a[3]), "r"(b0), "r"(b1));
}
__device__ __forceinline__ int swz(int col, int row) {
    return col ^ (((row & 7) << 2) | ((row >> 3) & 3));
}

// ===========================================================================
// Fragment-major layouts
//   A (row-major [M,K] logical) -> blocks of 16m x 8k, 512B each:
//     blk = (m>>4)*(K>>3) + (k>>3)
//     inner float = ((m&7)*4 + (k&3))*4 + ((k>>2)&1)*2 + ((m>>3)&1)
//     (lane (m&7)*4+(k&3) holds its 4 mma A-frag words contiguously)
//   B (logical [K,N], col "n" is mma N) -> blocks of 8n x 8k, 256B each:
//     blk = (n>>3)*(K>>3) + (k>>3)
//     inner float = ((n&7)*4 + (k&3))*2 + ((k>>2)&1)
// ===========================================================================
__global__ void xfrag_kernel(const float* __restrict__ in, float* __restrict__ out,
                             int M, int K)
{
    int id = blockIdx.x * blockDim.x + threadIdx.x;
    if (id < M * K) {
        int m = id / K, k = id % K;
        float v = __uint_as_float(f2tf32(in[id]));
        int blk = (m >> 4) * (K >> 3) + (k >> 3);
        int inner = ((m & 7) * 4 + (k & 3)) * 4 + ((k >> 2) & 1) * 2 + ((m >> 3) & 1);
        out[(size_t)blk * 128 + inner] = v;
    }
}
__global__ void wfrag_kernel(const float* __restrict__ in, float* __restrict__ out,
                             int K, int N)
{
    int id = blockIdx.x * blockDim.x + threadIdx.x;
    if (id < K * N) {
        int k = id / N, n = id % N;
        float v = __uint_as_float(f2tf32(in[id]));
        int blk = (n >> 3) * (K >> 3) + (k >> 3);
        int inner = ((n & 7) * 4 + (k & 3)) * 2 + ((k >> 2) & 1);
        out[(size_t)blk * 64 + inner] = v;
    }
}

// ===========================================================================
// Pre-pass: K/V fp32 -> swizzled bf16 hi/lo gmem tiles (unchanged)
// ===========================================================================
__global__ __launch_bounds__(128)
void kvconv_kernel(const float* __restrict__ qkv,
                   uint32_t* __restrict__ kw, uint32_t* __restrict__ vw)
{
    const int tid = threadIdx.x;
    const int jt  = blockIdx.x;
    const int bh  = blockIdx.y;
    const int b   = bh >> 4;
    const int h   = bh & 15;
    const int k0  = jt * 64;
    const float* base = qkv + (size_t)(b * LSEQ) * NQKV + h * HDIM;

    uint32_t* kh = kw + ((size_t)(bh * 32 + jt) * 2) * 2048;
    uint32_t* kl = kh + 2048;
    uint32_t* vh = vw + ((size_t)(bh * 32 + jt) * 2) * 2048;
    uint32_t* vl = vh + 2048;

    {
        const int j    = tid & 63;
        const int half = tid >> 6;
        const float* src = base + DMOD + (size_t)(k0 + j) * NQKV + half * 32;
        #pragma unroll
        for (int i = 0; i < 8; i++) {
            float4 k4 = *(const float4*)&src[4 * i];
            uint32_t h0 = pk_bf16(k4.x, k4.y);
            uint32_t h1 = pk_bf16(k4.z, k4.w);
            int c = half * 16 + 2 * i;
            kh[j * 32 + swz(c, j)]     = h0;
            kh[j * 32 + swz(c + 1, j)] = h1;
            kl[j * 32 + swz(c, j)]     = pk_bf16(k4.x - bflo(h0), k4.y - bfhi(h0));
            kl[j * 32 + swz(c + 1, j)] = pk_bf16(k4.z - bflo(h1), k4.w - bfhi(h1));
        }
    }
    {
        const int jp = tid & 31;
        const int d0 = (tid >> 5) << 4;
        const float* r0 = base + 2 * DMOD + (size_t)(k0 + 2 * jp) * NQKV + d0;
        const float* r1 = r0 + NQKV;
        #pragma unroll
        for (int i4 = 0; i4 < 4; i4++) {
            float4 x = *(const float4*)&r0[4 * i4];
            float4 yv = *(const float4*)&r1[4 * i4];
            float xs[4] = {x.x, x.y, x.z, x.w};
            float ys[4] = {yv.x, yv.y, yv.z, yv.w};
            #pragma unroll
            for (int e = 0; e < 4; e++) {
                int d = d0 + 4 * i4 + e;
                uint32_t hi = pk_bf16(xs[e], ys[e]);
                vh[d * 32 + swz(jp, d)] = hi;
                vl[d * 32 + swz(jp, d)] = pk_bf16(xs[e] - bflo(hi), ys[e] - bfhi(hi));
            }
        }
    }
}

// ===========================================================================
// tf32 tensor-core GEMM + bias, FRAG-MAJOR A/B inputs.
// Per-fragment loads: 1x LDS.128 (A), 1x LDS.64 (B). Single sync per chunk
// (4-stage rotation makes the trailing barrier redundant).
// ===========================================================================
#define GSTAGES 4
#define GBK 16
#define A_STAGE_B 8192            // 8 mblocks x 2 kblocks x 512B
#define B_STAGE_B 8192            // 16 nblocks x 2 kblocks x 256B
#define ST_B (A_STAGE_B + B_STAGE_B)
#define GEMM_SMEM (GSTAGES * ST_B)    // 65536

__global__ __launch_bounds__(256, 2)
void gemm_tc(const float* __restrict__ A, const float* __restrict__ W,
             const float* __restrict__ bias, float* __restrict__ C,
             int M, int N, int K)
{
    extern __shared__ __align__(16) float sm_f[];
    const uint32_t sm_b = smem_u32(sm_f);

    const int tid  = threadIdx.x;
    const int wid  = tid >> 5;
    const int lane = tid & 31;
    const int grp  = lane >> 2;
    const int qid  = lane & 3;
    const int wm   = wid >> 2;
    const int wn   = wid & 3;
    const int m0   = blockIdx.y * 128;
    const int n0   = blockIdx.x * 128;
    const int NCHUNK = K / GBK;
    const int KB = K >> 3;          // k-blocks per row of blocks

    float acc[4][4][4];
    #pragma unroll
    for (int mi = 0; mi < 4; mi++)
        #pragma unroll
        for (int ni = 0; ni < 4; ni++)
            #pragma unroll
            for (int q = 0; q < 4; q++) acc[mi][ni][q] = 0.0f;

    auto load_stage = [&](int s, int kc0) {
        const uint32_t as = sm_b + s * ST_B;
        const uint32_t bs = as + A_STAGE_B;
        const int kb = kc0 >> 3;
        #pragma unroll
        for (int i = 0; i < 2; i++) {
            int id   = tid + i * 256;      // 0..511
            int mblk = id >> 6;            // 0..7
            int off  = id & 63;            // 16B units within 1KB (2 kblocks)
            const float* src = A + ((size_t)((m0 >> 4) + mblk) * KB + kb) * 128 + off * 4;
            cp_async16(as + mblk * 1024 + off * 16, src);
        }
        #pragma unroll
        for (int i = 0; i < 2; i++) {
            int id   = tid + i * 256;      // 0..511
            int nblk = id >> 5;            // 0..15
            int off  = id & 31;            // 16B units within 512B (2 kblocks)
            const float* src = W + ((size_t)((n0 >> 3) + nblk) * KB + kb) * 64 + off * 4;
            cp_async16(bs + nblk * 512 + off * 16, src);
        }
        cp_commit();
    };

    #pragma unroll
    for (int s = 0; s < GSTAGES - 1; s++) load_stage(s, s * GBK);

    for (int c = 0; c < NCHUNK; c++) {
        CP_WAIT(GSTAGES - 2);
        __syncthreads();   // stage c ready for ALL; also closes reads of stage c-1
        {
            int nc = c + GSTAGES - 1;
            if (nc < NCHUNK) load_stage(nc % GSTAGES, nc * GBK);
        }

        const float* as = sm_f + (c % GSTAGES) * (ST_B / 4);
        const float* bs = as + A_STAGE_B / 4;

        #pragma unroll
        for (int ks = 0; ks < 2; ks++) {
            uint32_t af[4][4], bf[4][2];
            #pragma unroll
            for (int mi = 0; mi < 4; mi++) {
                const float4 fa = *(const float4*)
                    &as[((wm * 4 + mi) * 2 + ks) * 128 + lane * 4];
                af[mi][0] = __float_as_uint(fa.x);
                af[mi][1] = __float_as_uint(fa.y);
                af[mi][2] = __float_as_uint(fa.z);
                af[mi][3] = __float_as_uint(fa.w);
            }
            #pragma unroll
            for (int ni = 0; ni < 4; ni++) {
                const float2 fb = *(const float2*)
                    &bs[((wn * 4 + ni) * 2 + ks) * 64 + lane * 2];
                bf[ni][0] = __float_as_uint(fb.x);
                bf[ni][1] = __float_as_uint(fb.y);
            }
            #pragma unroll
            for (int mi = 0; mi < 4; mi++)
                #pragma unroll
                for (int ni = 0; ni < 4; ni++)
                    mma_tf32(acc[mi][ni], af[mi], bf[ni]);
        }
        // no trailing sync: next write to this stage is gated by the next
        // iteration's top __syncthreads (4-stage rotation)
    }

    #pragma unroll
    for (int mi = 0; mi < 4; mi++) {
        int r0 = m0 + wm * 64 + mi * 16 + grp;
        #pragma unroll
        for (int ni = 0; ni < 4; ni++) {
            int col = n0 + wn * 32 + ni * 8 + qid * 2;
            float2 bv = *(const float2*)&bias[col];
            float2 o0, o1;
            o0.x = acc[mi][ni][0] + bv.x;  o0.y = acc[mi][ni][1] + bv.y;
            o1.x = acc[mi][ni][2] + bv.x;  o1.y = acc[mi][ni][3] + bv.y;
            *(float2*)&C[(size_t)r0 * N + col]       = o0;
            *(float2*)&C[(size_t)(r0 + 8) * N + col] = o1;
        }
    }
}

// ===========================================================================
// Flash-attention (causal), bf16 3-term mma.sync; K/V pre-converted in gmem.
// Round-12: single sync per tile (prefetch issued after the barrier, still
// overlapping the MMAs); epilogue writes y in FRAG-A layout for the proj GEMM.
// ===========================================================================
#define ATT_STAGE_W 8192
#define ATTN_SMEM (2 * ATT_STAGE_W * 4)   // 65536 B

__global__ __launch_bounds__(128, 3)
void attn_mma(const float* __restrict__ qkv,
              const uint32_t* __restrict__ kw, const uint32_t* __restrict__ vw,
              float* __restrict__ y)
{
    extern __shared__ __align__(16) uint32_t sm_w[];
    const uint32_t sm_b = smem_u32(sm_w);

    const int tid  = threadIdx.x;
    const int wid  = tid >> 5;
    const int lane = tid & 31;
    const int grp  = lane >> 2;
    const int qid  = lane & 3;

    const int qt = gridDim.x - 1 - blockIdx.x;
    const int bh = blockIdx.y;
    const int b  = bh >> 4;
    const int h  = bh & 15;
    const int q0 = qt * 64;

    const float* base = qkv + (size_t)(b * LSEQ) * NQKV + h * HDIM;
    const char* gk_base = (const char*)(kw + (size_t)bh * 32 * 2 * 2048);
    const char* gv_base = (const char*)(vw + (size_t)bh * 32 * 2 * 2048);

    // ---- Q fragments (hi/lo bf16) ----
    uint32_t qh[4][4], ql[4][4];
    const int i0 = q0 + wid * 16 + grp;
    #pragma unroll
    for (int kc = 0; kc < 4; kc++)
        #pragma unroll
        for (int hh = 0; hh < 2; hh++)
            #pragma unroll
            for (int rr = 0; rr < 2; rr++) {
                const float* p = base + (size_t)(i0 + 8 * rr) * NQKV
                               + kc * 16 + hh * 8 + 2 * qid;
                float2 v = *(const float2*)p;
                uint32_t hi = pk_bf16(v.x, v.y);
                qh[kc][2 * hh + rr] = hi;
                ql[kc][2 * hh + rr] = pk_bf16(v.x - bflo(hi), v.y - bfhi(hi));
            }

    float o[8][4];
    #pragma unroll
    for (int nt = 0; nt < 8; nt++)
        #pragma unroll
        for (int c = 0; c < 4; c++) o[nt][c] = 0.0f;
    float m0f = -1e30f, m1f = -1e30f, l0 = 0.0f, l1 = 0.0f;

    auto prefetch = [&](int kt, int s) {
        const char* gk = gk_base + (size_t)kt * 16384;
        const char* gv = gv_base + (size_t)kt * 16384;
        const uint32_t dst = sm_b + s * (ATT_STAGE_W * 4);
        #pragma unroll
        for (int i = 0; i < 16; i++) {
            int id = tid + i * 128;
            const char* src = (id < 1024) ? (gk + id * 16)
                                          : (gv + (id - 1024) * 16);
            cp_async16(dst + id * 16, src);
        }
        cp_commit();
    };

    prefetch(0, 0);

    for (int kt = 0; kt <= qt; kt++) {
        const int k0 = kt * 64;
        const int s  = kt & 1;
        CP_WAIT(0);
        __syncthreads();   // stage s ready; also closes last tile's reads of s^1
        if (kt < qt) prefetch(kt + 1, s ^ 1);   // overlaps the MMAs below

        const uint32_t* KhiW = sm_w + s * ATT_STAGE_W;
        const uint32_t* KloW = KhiW + 2048;
        const uint32_t* VhW  = KhiW + 4096;
        const uint32_t* VlW  = KhiW + 6144;

        // ---- S = Q @ K^T (3-term bf16) ----
        float sreg[8][4];
        #pragma unroll
        for (int nt = 0; nt < 8; nt++)
            #pragma unroll
            for (int c = 0; c < 4; c++) sreg[nt][c] = 0.0f;

        #pragma unroll
        for (int nt = 0; nt < 8; nt++) {
            const int j = nt * 8 + grp;
            const uint32_t* kh = KhiW + j * 32;
            const uint32_t* kl = KloW + j * 32;
            #pragma unroll
            for (int kc = 0; kc < 4; kc++) {
                uint32_t b0h = kh[swz(8 * kc + qid, j)];
                uint32_t b1h = kh[swz(8 * kc + 4 + qid, j)];
                uint32_t b0l = kl[swz(8 * kc + qid, j)];
                uint32_t b1l = kl[swz(8 * kc + 4 + qid, j)];
                mma_bf16(sreg[nt], qh[kc], b0h, b1h);
                mma_bf16(sreg[nt], qh[kc], b0l, b1l);
                mma_bf16(sreg[nt], ql[kc], b0h, b1h);
            }
        }

        // ---- scale + causal mask ----
        const float scale = 0.125f;
        if (kt == qt) {
            #pragma unroll
            for (int nt = 0; nt < 8; nt++)
                #pragma unroll
                for (int c = 0; c < 4; c++) {
                    int j = k0 + nt * 8 + 2 * qid + (c & 1);
                    int i = (c < 2) ? i0 : (i0 + 8);
                    float sv = sreg[nt][c] * scale;
                    if (j > i) sv = -1e30f;
                    sreg[nt][c] = sv;
                }
        } else {
            #pragma unroll
            for (int nt = 0; nt < 8; nt++)
                #pragma unroll
                for (int c = 0; c < 4; c++) sreg[nt][c] *= scale;
        }

        // ---- online softmax ----
        float mx0 = -1e30f, mx1 = -1e30f;
        #pragma unroll
        for (int nt = 0; nt < 8; nt++) {
            mx0 = fmaxf(mx0, fmaxf(sreg[nt][0], sreg[nt][1]));
            mx1 = fmaxf(mx1, fmaxf(sreg[nt][2], sreg[nt][3]));
        }
        #pragma unroll
        for (int off = 1; off <= 2; off <<= 1) {
            mx0 = fmaxf(mx0, __shfl_xor_sync(0xffffffffu, mx0, off));
            mx1 = fmaxf(mx1, __shfl_xor_sync(0xffffffffu, mx1, off));
        }
        float mn0 = fmaxf(m0f, mx0);
        float mn1 = fmaxf(m1f, mx1);
        float a0 = __expf(m0f - mn0);
        float a1 = __expf(m1f - mn1);
        m0f = mn0; m1f = mn1;
        #pragma unroll
        for (int nt = 0; nt < 8; nt++) {
            o[nt][0] *= a0;  o[nt][1] *= a0;
            o[nt][2] *= a1;  o[nt][3] *= a1;
        }

        // ---- exp, repack, PV mma (3-term) ----
        float rs0 = 0.0f, rs1 = 0.0f;
        #pragma unroll
        for (int kc2 = 0; kc2 < 4; kc2++) {
            uint32_t ph[4], pl[4];
            #pragma unroll
            for (int part = 0; part < 2; part++) {
                const int nt = kc2 * 2 + part;
                float p0 = __expf(sreg[nt][0] - mn0);
                float p1 = __expf(sreg[nt][1] - mn0);
                float p2 = __expf(sreg[nt][2] - mn1);
                float p3 = __expf(sreg[nt][3] - mn1);
                rs0 += p0 + p1;
                rs1 += p2 + p3;
                uint32_t u01 = pk_bf16(p0, p1);
                uint32_t u23 = pk_bf16(p2, p3);
                ph[2 * part]     = u01;
                ph[2 * part + 1] = u23;
                pl[2 * part]     = pk_bf16(p0 - bflo(u01), p1 - bfhi(u01));
                pl[2 * part + 1] = pk_bf16(p2 - bflo(u23), p3 - bfhi(u23));
            }
            #pragma unroll
            for (int ont = 0; ont < 8; ont++) {
                const int d = ont * 8 + grp;
                const uint32_t* vh = VhW + d * 32;
                const uint32_t* vl = VlW + d * 32;
                uint32_t b0h = vh[swz(8 * kc2 + qid, d)];
                uint32_t b1h = vh[swz(8 * kc2 + 4 + qid, d)];
                uint32_t b0l = vl[swz(8 * kc2 + qid, d)];
                uint32_t b1l = vl[swz(8 * kc2 + 4 + qid, d)];
                mma_bf16(o[ont], ph, b0h, b1h);
                mma_bf16(o[ont], ph, b0l, b1l);
                mma_bf16(o[ont], pl, b0h, b1h);
            }
        }
        #pragma unroll
        for (int off = 1; off <= 2; off <<= 1) {
            rs0 += __shfl_xor_sync(0xffffffffu, rs0, off);
            rs1 += __shfl_xor_sync(0xffffffffu, rs1, off);
        }
        l0 = l0 * a0 + rs0;
        l1 = l1 * a1 + rs1;
        // no trailing sync: top-of-loop sync gates the next write to s^1
    }

    // ---- epilogue: tf32-rounded store in FRAG-A layout (proj GEMM input) ----
    const float inv0 = 1.0f / l0;
    const float inv1 = 1.0f / l1;
    #pragma unroll
    for (int ont = 0; ont < 8; ont++) {
        #pragma unroll
        for (int c = 0; c < 4; c++) {
            int col = h * HDIM + ont * 8 + 2 * qid + (c & 1);
            int m   = b * LSEQ + i0 + ((c >> 1) << 3);
            float val = (c < 2) ? o[ont][c] * inv0 : o[ont][c] * inv1;
            int blk = (m >> 4) * (DMOD >> 3) + (col >> 3);
            int inner = ((m & 7) * 4 + (col & 3)) * 4
                      + ((col >> 2) & 1) * 2 + ((m >> 3) & 1);
            y[(size_t)blk * 128 + inner] = __uint_as_float(f2tf32(val));
        }
    }
}

// ===========================================================================
// Launch
// ===========================================================================
extern "C" void kernel_launch(void* const* d_in, const int* in_sizes, int n_in,
                              void* d_out, int out_size)
{
    (void)in_sizes; (void)n_in; (void)out_size;
    const float* x     = (const float*)d_in[0];
    const float* Wqkv  = (const float*)d_in[1];
    const float* bqkv  = (const float*)d_in[2];
    const float* Wproj = (const float*)d_in[3];
    const float* bproj = (const float*)d_in[4];
    float* out = (float*)d_out;

    float *qkvp, *yp, *xr, *wqkvr, *wprojr;
    uint32_t *kwp, *vwp;
    cudaGetSymbolAddress((void**)&qkvp, g_qkv);
    cudaGetSymbolAddress((void**)&yp, g_y);
    cudaGetSymbolAddress((void**)&xr, g_xr);
    cudaGetSymbolAddress((void**)&wqkvr, g_wqkvr);
    cudaGetSymbolAddress((void**)&wprojr, g_wprojr);
    cudaGetSymbolAddress((void**)&kwp, g_kw);
    cudaGetSymbolAddress((void**)&vwp, g_vw);

    static bool attr_set = false;
    if (!attr_set) {
        cudaFuncSetAttribute(gemm_tc, cudaFuncAttributeMaxDynamicSharedMemorySize,
                             GEMM_SMEM);
        cudaFuncSetAttribute(attn_mma, cudaFuncAttributeMaxDynamicSharedMemorySize,
                             ATTN_SMEM);
        attr_set = true;
    }

    // Pre-passes: round + relayout into fragment-major operand buffers
    {
        int nx = MROWS * DMOD;
        int nq = DMOD * NQKV;
        int np = DMOD * DMOD;
        xfrag_kernel<<<(nx + 255) / 256, 256>>>(x, xr, MROWS, DMOD);
        wfrag_kernel<<<(nq + 255) / 256, 256>>>(Wqkv, wqkvr, DMOD, NQKV);
        wfrag_kernel<<<(np + 255) / 256, 256>>>(Wproj, wprojr, DMOD, DMOD);
    }

    // QKV projection
    gemm_tc<<<dim3(NQKV / 128, MROWS / 128), 256, GEMM_SMEM>>>(
        xr, wqkvr, bqkv, qkvp, MROWS, NQKV, DMOD);
    // K/V -> swizzled bf16 hi/lo tiles
    kvconv_kernel<<<dim3(32, 64), 128>>>(qkvp, kwp, vwp);
    // Causal flash attention (epilogue emits frag-A y)
    attn_mma<<<dim3(LSEQ / 64, BSZ * NHEAD), 128, ATTN_SMEM>>>(qkvp, kwp, vwp, yp);
    // Output projection
    gemm_tc<<<dim3(DMOD / 128, MROWS / 128), 256, GEMM_SMEM>>>(
        yp, wprojr, bproj, out, MROWS, DMOD, DMOD);
}

// round 13
// speedup vs baseline: 3.9003x; 1.0555x over previous
#include <cuda_runtime.h>
#include <cuda_bf16.h>
#include <math.h>
#include <stdint.h>

// Problem constants
#define BSZ   4
#define LSEQ  2048
#define DMOD  1024
#define NHEAD 16
#define HDIM  64
#define MROWS (BSZ * LSEQ)      // 8192
#define NQKV  (3 * DMOD)        // 3072

// Scratch (allocation-free rule: device globals)
__device__ __align__(16) float g_qkv[(size_t)MROWS * NQKV];   // [B*L, 3D] row-major
__device__ __align__(16) float g_y[(size_t)MROWS * DMOD];     // attn out, FRAG-A layout
__device__ __align__(16) float g_xr[(size_t)MROWS * DMOD];    // x rounded, FRAG-A layout
__device__ __align__(16) float g_wqkvr[(size_t)DMOD * NQKV];  // Wqkv rounded, FRAG-B
__device__ __align__(16) float g_wprojr[(size_t)DMOD * DMOD]; // Wproj rounded, FRAG-B
// Pre-converted KV: per (bh, jtile): [Khi 2048w][Klo 2048w], frag-unit tiles
__device__ __align__(16) uint32_t g_kw[(size_t)64 * 32 * 2 * 2048];
__device__ __align__(16) uint32_t g_vw[(size_t)64 * 32 * 2 * 2048];

// ===========================================================================
// Helpers
// ===========================================================================
__device__ __forceinline__ uint32_t smem_u32(const void* p) {
    uint32_t a;
    asm("{ .reg .u64 t; cvta.to.shared.u64 t, %1; cvt.u32.u64 %0, t; }"
        : "=r"(a) : "l"(p));
    return a;
}
__device__ __forceinline__ void cp_async16(uint32_t dst, const void* src) {
    asm volatile("cp.async.cg.shared.global [%0], [%1], 16;"
                 :: "r"(dst), "l"(src) : "memory");
}
__device__ __forceinline__ void cp_commit() {
    asm volatile("cp.async.commit_group;" ::: "memory");
}
#define CP_WAIT(n) asm volatile("cp.async.wait_group %0;" :: "n"(n) : "memory")

__device__ __forceinline__ uint32_t f2tf32(float f) {
    uint32_t r;
    asm("cvt.rna.tf32.f32 %0, %1;" : "=r"(r) : "f"(f));
    return r;
}
__device__ __forceinline__ void mma_tf32(float* c, const uint32_t* a, const uint32_t* b) {
    asm volatile(
        "mma.sync.aligned.m16n8k8.row.col.f32.tf32.tf32.f32 "
        "{%0,%1,%2,%3}, {%4,%5,%6,%7}, {%8,%9}, {%0,%1,%2,%3};\n"
        : "+f"(c[0]), "+f"(c[1]), "+f"(c[2]), "+f"(c[3])
        : "r"(a[0]), "r"(a[1]), "r"(a[2]), "r"(a[3]), "r"(b[0]), "r"(b[1]));
}
__device__ __forceinline__ uint32_t pk_bf16(float x, float y) {
    uint32_t r;
    asm("cvt.rn.bf16x2.f32 %0, %1, %2;" : "=r"(r) : "f"(y), "f"(x));
    return r;
}
__device__ __forceinline__ float bflo(uint32_t u) { return __uint_as_float(u << 16); }
__device__ __forceinline__ float bfhi(uint32_t u) { return __uint_as_float(u & 0xffff0000u); }

__device__ __forceinline__ void mma_bf16(float* c, const uint32_t* a,
                                         uint32_t b0, uint32_t b1) {
    asm volatile(
        "mma.sync.aligned.m16n8k16.row.col.f32.bf16.bf16.f32 "
        "{%0,%1,%2,%3}, {%4,%5,%6,%7}, {%8,%9}, {%0,%1,%2,%3};\n"
        : "+f"(c[0]), "+f"(c[1]), "+f"(c[2]), "+f"(c[3])
        : "r"(a[0]), "r"(a[1]), "r"(a[2]), "r"(a[3]), "r"(b0), "r"(b1));
}

// K/V tile word address: logical col c = 8*kc + 4*t + qid  (t = b0/b1)
// packed so lane qid's fragments for kc pair (2i, 2i+1) form one 16B unit,
// unit index XOR-rotated by row&7 for conflict-free LDS.128.
__device__ __forceinline__ int kaddr(int c, int row) {
    int kc = c >> 3, t = (c >> 2) & 1, q = c & 3;
    int u = q * 2 + (kc >> 1);
    int w = (kc & 1) * 2 + t;
    return row * 32 + ((u ^ (row & 7)) << 2) + w;
}

// ===========================================================================
// Fragment-major GEMM operand layouts (unchanged from round 12)
// ===========================================================================
__global__ void xfrag_kernel(const float* __restrict__ in, float* __restrict__ out,
                             int M, int K)
{
    int id = blockIdx.x * blockDim.x + threadIdx.x;
    if (id < M * K) {
        int m = id / K, k = id % K;
        float v = __uint_as_float(f2tf32(in[id]));
        int blk = (m >> 4) * (K >> 3) + (k >> 3);
        int inner = ((m & 7) * 4 + (k & 3)) * 4 + ((k >> 2) & 1) * 2 + ((m >> 3) & 1);
        out[(size_t)blk * 128 + inner] = v;
    }
}
__global__ void wfrag_kernel(const float* __restrict__ in, float* __restrict__ out,
                             int K, int N)
{
    int id = blockIdx.x * blockDim.x + threadIdx.x;
    if (id < K * N) {
        int k = id / N, n = id % N;
        float v = __uint_as_float(f2tf32(in[id]));
        int blk = (n >> 3) * (K >> 3) + (k >> 3);
        int inner = ((n & 7) * 4 + (k & 3)) * 2 + ((k >> 2) & 1);
        out[(size_t)blk * 64 + inner] = v;
    }
}

// ===========================================================================
// Pre-pass: K/V fp32 -> frag-unit bf16 hi/lo gmem tiles
// ===========================================================================
__global__ __launch_bounds__(128)
void kvconv_kernel(const float* __restrict__ qkv,
                   uint32_t* __restrict__ kw, uint32_t* __restrict__ vw)
{
    const int tid = threadIdx.x;
    const int jt  = blockIdx.x;
    const int bh  = blockIdx.y;
    const int b   = bh >> 4;
    const int h   = bh & 15;
    const int k0  = jt * 64;
    const float* base = qkv + (size_t)(b * LSEQ) * NQKV + h * HDIM;

    uint32_t* kh = kw + ((size_t)(bh * 32 + jt) * 2) * 2048;
    uint32_t* kl = kh + 2048;
    uint32_t* vh = vw + ((size_t)(bh * 32 + jt) * 2) * 2048;
    uint32_t* vl = vh + 2048;

    {
        const int j    = tid & 63;
        const int half = tid >> 6;
        const float* src = base + DMOD + (size_t)(k0 + j) * NQKV + half * 32;
        #pragma unroll
        for (int i = 0; i < 8; i++) {
            float4 k4 = *(const float4*)&src[4 * i];
            uint32_t h0 = pk_bf16(k4.x, k4.y);
            uint32_t h1 = pk_bf16(k4.z, k4.w);
            int c = half * 16 + 2 * i;
            kh[kaddr(c, j)]     = h0;
            kh[kaddr(c + 1, j)] = h1;
            kl[kaddr(c, j)]     = pk_bf16(k4.x - bflo(h0), k4.y - bfhi(h0));
            kl[kaddr(c + 1, j)] = pk_bf16(k4.z - bflo(h1), k4.w - bfhi(h1));
        }
    }
    {
        const int jp = tid & 31;
        const int d0 = (tid >> 5) << 4;
        const float* r0 = base + 2 * DMOD + (size_t)(k0 + 2 * jp) * NQKV + d0;
        const float* r1 = r0 + NQKV;
        #pragma unroll
        for (int i4 = 0; i4 < 4; i4++) {
            float4 x = *(const float4*)&r0[4 * i4];
            float4 yv = *(const float4*)&r1[4 * i4];
            float xs[4] = {x.x, x.y, x.z, x.w};
            float ys[4] = {yv.x, yv.y, yv.z, yv.w};
            #pragma unroll
            for (int e = 0; e < 4; e++) {
                int d = d0 + 4 * i4 + e;
                uint32_t hi = pk_bf16(xs[e], ys[e]);
                vh[kaddr(jp, d)] = hi;
                vl[kaddr(jp, d)] = pk_bf16(xs[e] - bflo(hi), ys[e] - bfhi(hi));
            }
        }
    }
}

// ===========================================================================
// tf32 tensor-core GEMM + bias, FRAG-MAJOR A/B inputs (unchanged round 12)
// ===========================================================================
#define GSTAGES 4
#define GBK 16
#define A_STAGE_B 8192
#define B_STAGE_B 8192
#define ST_B (A_STAGE_B + B_STAGE_B)
#define GEMM_SMEM (GSTAGES * ST_B)    // 65536

__global__ __launch_bounds__(256, 2)
void gemm_tc(const float* __restrict__ A, const float* __restrict__ W,
             const float* __restrict__ bias, float* __restrict__ C,
             int M, int N, int K)
{
    extern __shared__ __align__(16) float sm_f[];
    const uint32_t sm_b = smem_u32(sm_f);

    const int tid  = threadIdx.x;
    const int wid  = tid >> 5;
    const int lane = tid & 31;
    const int grp  = lane >> 2;
    const int qid  = lane & 3;
    const int wm   = wid >> 2;
    const int wn   = wid & 3;
    const int m0   = blockIdx.y * 128;
    const int n0   = blockIdx.x * 128;
    const int NCHUNK = K / GBK;
    const int KB = K >> 3;

    float acc[4][4][4];
    #pragma unroll
    for (int mi = 0; mi < 4; mi++)
        #pragma unroll
        for (int ni = 0; ni < 4; ni++)
            #pragma unroll
            for (int q = 0; q < 4; q++) acc[mi][ni][q] = 0.0f;

    auto load_stage = [&](int s, int kc0) {
        const uint32_t as = sm_b + s * ST_B;
        const uint32_t bs = as + A_STAGE_B;
        const int kb = kc0 >> 3;
        #pragma unroll
        for (int i = 0; i < 2; i++) {
            int id   = tid + i * 256;
            int mblk = id >> 6;
            int off  = id & 63;
            const float* src = A + ((size_t)((m0 >> 4) + mblk) * KB + kb) * 128 + off * 4;
            cp_async16(as + mblk * 1024 + off * 16, src);
        }
        #pragma unroll
        for (int i = 0; i < 2; i++) {
            int id   = tid + i * 256;
            int nblk = id >> 5;
            int off  = id & 31;
            const float* src = W + ((size_t)((n0 >> 3) + nblk) * KB + kb) * 64 + off * 4;
            cp_async16(bs + nblk * 512 + off * 16, src);
        }
        cp_commit();
    };

    #pragma unroll
    for (int s = 0; s < GSTAGES - 1; s++) load_stage(s, s * GBK);

    for (int c = 0; c < NCHUNK; c++) {
        CP_WAIT(GSTAGES - 2);
        __syncthreads();
        {
            int nc = c + GSTAGES - 1;
            if (nc < NCHUNK) load_stage(nc % GSTAGES, nc * GBK);
        }

        const float* as = sm_f + (c % GSTAGES) * (ST_B / 4);
        const float* bs = as + A_STAGE_B / 4;

        #pragma unroll
        for (int ks = 0; ks < 2; ks++) {
            uint32_t af[4][4], bf[4][2];
            #pragma unroll
            for (int mi = 0; mi < 4; mi++) {
                const float4 fa = *(const float4*)
                    &as[((wm * 4 + mi) * 2 + ks) * 128 + lane * 4];
                af[mi][0] = __float_as_uint(fa.x);
                af[mi][1] = __float_as_uint(fa.y);
                af[mi][2] = __float_as_uint(fa.z);
                af[mi][3] = __float_as_uint(fa.w);
            }
            #pragma unroll
            for (int ni = 0; ni < 4; ni++) {
                const float2 fb = *(const float2*)
                    &bs[((wn * 4 + ni) * 2 + ks) * 64 + lane * 2];
                bf[ni][0] = __float_as_uint(fb.x);
                bf[ni][1] = __float_as_uint(fb.y);
            }
            #pragma unroll
            for (int mi = 0; mi < 4; mi++)
                #pragma unroll
                for (int ni = 0; ni < 4; ni++)
                    mma_tf32(acc[mi][ni], af[mi], bf[ni]);
        }
    }

    #pragma unroll
    for (int mi = 0; mi < 4; mi++) {
        int r0 = m0 + wm * 64 + mi * 16 + grp;
        #pragma unroll
        for (int ni = 0; ni < 4; ni++) {
            int col = n0 + wn * 32 + ni * 8 + qid * 2;
            float2 bv = *(const float2*)&bias[col];
            float2 o0, o1;
            o0.x = acc[mi][ni][0] + bv.x;  o0.y = acc[mi][ni][1] + bv.y;
            o1.x = acc[mi][ni][2] + bv.x;  o1.y = acc[mi][ni][3] + bv.y;
            *(float2*)&C[(size_t)r0 * N + col]       = o0;
            *(float2*)&C[(size_t)(r0 + 8) * N + col] = o1;
        }
    }
}

// ===========================================================================
// Flash-attention (causal), bf16 3-term mma.sync; frag-unit K/V tiles.
// Round-13: fragment loads are LDS.128 (2 per row per hi/lo), zero in-loop
// swizzle ALU. PV: P-fragments for all kc2 precomputed, V rows loaded once.
// ===========================================================================
#define ATT_STAGE_W 8192
#define ATTN_SMEM (2 * ATT_STAGE_W * 4)   // 65536 B

__global__ __launch_bounds__(128, 3)
void attn_mma(const float* __restrict__ qkv,
              const uint32_t* __restrict__ kw, const uint32_t* __restrict__ vw,
              float* __restrict__ y)
{
    extern __shared__ __align__(16) uint32_t sm_w[];
    const uint32_t sm_b = smem_u32(sm_w);

    const int tid  = threadIdx.x;
    const int wid  = tid >> 5;
    const int lane = tid & 31;
    const int grp  = lane >> 2;
    const int qid  = lane & 3;

    const int qt = gridDim.x - 1 - blockIdx.x;
    const int bh = blockIdx.y;
    const int b  = bh >> 4;
    const int h  = bh & 15;
    const int q0 = qt * 64;

    const float* base = qkv + (size_t)(b * LSEQ) * NQKV + h * HDIM;
    const char* gk_base = (const char*)(kw + (size_t)bh * 32 * 2 * 2048);
    const char* gv_base = (const char*)(vw + (size_t)bh * 32 * 2 * 2048);

    // ---- Q fragments (hi/lo bf16) ----
    uint32_t qh[4][4], ql[4][4];
    const int i0 = q0 + wid * 16 + grp;
    #pragma unroll
    for (int kc = 0; kc < 4; kc++)
        #pragma unroll
        for (int hh = 0; hh < 2; hh++)
            #pragma unroll
            for (int rr = 0; rr < 2; rr++) {
                const float* p = base + (size_t)(i0 + 8 * rr) * NQKV
                               + kc * 16 + hh * 8 + 2 * qid;
                float2 v = *(const float2*)p;
                uint32_t hi = pk_bf16(v.x, v.y);
                qh[kc][2 * hh + rr] = hi;
                ql[kc][2 * hh + rr] = pk_bf16(v.x - bflo(hi), v.y - bfhi(hi));
            }

    float o[8][4];
    #pragma unroll
    for (int nt = 0; nt < 8; nt++)
        #pragma unroll
        for (int c = 0; c < 4; c++) o[nt][c] = 0.0f;
    float m0f = -1e30f, m1f = -1e30f, l0 = 0.0f, l1 = 0.0f;

    auto prefetch = [&](int kt, int s) {
        const char* gk = gk_base + (size_t)kt * 16384;
        const char* gv = gv_base + (size_t)kt * 16384;
        const uint32_t dst = sm_b + s * (ATT_STAGE_W * 4);
        #pragma unroll
        for (int i = 0; i < 16; i++) {
            int id = tid + i * 128;
            const char* src = (id < 1024) ? (gk + id * 16)
                                          : (gv + (id - 1024) * 16);
            cp_async16(dst + id * 16, src);
        }
        cp_commit();
    };

    prefetch(0, 0);

    // Unit offsets for this lane's fragment loads (words): u0 = 2*qid, u1 = 2*qid+1
    const int u0 = qid * 2;
    const int u1 = qid * 2 + 1;

    for (int kt = 0; kt <= qt; kt++) {
        const int k0 = kt * 64;
        const int s  = kt & 1;
        CP_WAIT(0);
        __syncthreads();
        if (kt < qt) prefetch(kt + 1, s ^ 1);

        const uint32_t* KhiW = sm_w + s * ATT_STAGE_W;
        const uint32_t* KloW = KhiW + 2048;
        const uint32_t* VhW  = KhiW + 4096;
        const uint32_t* VlW  = KhiW + 6144;

        // ---- S = Q @ K^T (3-term bf16), frag-unit loads ----
        float sreg[8][4];
        #pragma unroll
        for (int nt = 0; nt < 8; nt++)
            #pragma unroll
            for (int c = 0; c < 4; c++) sreg[nt][c] = 0.0f;

        #pragma unroll
        for (int nt = 0; nt < 8; nt++) {
            const int j  = nt * 8 + grp;
            const int x7 = j & 7;
            const uint32_t* kh = KhiW + j * 32;
            const uint32_t* kl = KloW + j * 32;
            uint4 h0 = *(const uint4*)&kh[(u0 ^ x7) << 2];
            uint4 h1 = *(const uint4*)&kh[(u1 ^ x7) << 2];
            uint4 g0 = *(const uint4*)&kl[(u0 ^ x7) << 2];
            uint4 g1 = *(const uint4*)&kl[(u1 ^ x7) << 2];
            mma_bf16(sreg[nt], qh[0], h0.x, h0.y);
            mma_bf16(sreg[nt], qh[0], g0.x, g0.y);
            mma_bf16(sreg[nt], ql[0], h0.x, h0.y);
            mma_bf16(sreg[nt], qh[1], h0.z, h0.w);
            mma_bf16(sreg[nt], qh[1], g0.z, g0.w);
            mma_bf16(sreg[nt], ql[1], h0.z, h0.w);
            mma_bf16(sreg[nt], qh[2], h1.x, h1.y);
            mma_bf16(sreg[nt], qh[2], g1.x, g1.y);
            mma_bf16(sreg[nt], ql[2], h1.x, h1.y);
            mma_bf16(sreg[nt], qh[3], h1.z, h1.w);
            mma_bf16(sreg[nt], qh[3], g1.z, g1.w);
            mma_bf16(sreg[nt], ql[3], h1.z, h1.w);
        }

        // ---- scale + causal mask ----
        const float scale = 0.125f;
        if (kt == qt) {
            #pragma unroll
            for (int nt = 0; nt < 8; nt++)
                #pragma unroll
                for (int c = 0; c < 4; c++) {
                    int j = k0 + nt * 8 + 2 * qid + (c & 1);
                    int i = (c < 2) ? i0 : (i0 + 8);
                    float sv = sreg[nt][c] * scale;
                    if (j > i) sv = -1e30f;
                    sreg[nt][c] = sv;
                }
        } else {
            #pragma unroll
            for (int nt = 0; nt < 8; nt++)
                #pragma unroll
                for (int c = 0; c < 4; c++) sreg[nt][c] *= scale;
        }

        // ---- online softmax ----
        float mx0 = -1e30f, mx1 = -1e30f;
        #pragma unroll
        for (int nt = 0; nt < 8; nt++) {
            mx0 = fmaxf(mx0, fmaxf(sreg[nt][0], sreg[nt][1]));
            mx1 = fmaxf(mx1, fmaxf(sreg[nt][2], sreg[nt][3]));
        }
        #pragma unroll
        for (int off = 1; off <= 2; off <<= 1) {
            mx0 = fmaxf(mx0, __shfl_xor_sync(0xffffffffu, mx0, off));
            mx1 = fmaxf(mx1, __shfl_xor_sync(0xffffffffu, mx1, off));
        }
        float mn0 = fmaxf(m0f, mx0);
        float mn1 = fmaxf(m1f, mx1);
        float a0 = __expf(m0f - mn0);
        float a1 = __expf(m1f - mn1);
        m0f = mn0; m1f = mn1;
        #pragma unroll
        for (int nt = 0; nt < 8; nt++) {
            o[nt][0] *= a0;  o[nt][1] *= a0;
            o[nt][2] *= a1;  o[nt][3] *= a1;
        }

        // ---- exp + repack ALL P fragments first ----
        float rs0 = 0.0f, rs1 = 0.0f;
        uint32_t ph[4][4], pl[4][4];
        #pragma unroll
        for (int kc2 = 0; kc2 < 4; kc2++) {
            #pragma unroll
            for (int part = 0; part < 2; part++) {
                const int nt = kc2 * 2 + part;
                float p0 = __expf(sreg[nt][0] - mn0);
                float p1 = __expf(sreg[nt][1] - mn0);
                float p2 = __expf(sreg[nt][2] - mn1);
                float p3 = __expf(sreg[nt][3] - mn1);
                rs0 += p0 + p1;
                rs1 += p2 + p3;
                uint32_t u01 = pk_bf16(p0, p1);
                uint32_t u23 = pk_bf16(p2, p3);
                ph[kc2][2 * part]     = u01;
                ph[kc2][2 * part + 1] = u23;
                pl[kc2][2 * part]     = pk_bf16(p0 - bflo(u01), p1 - bfhi(u01));
                pl[kc2][2 * part + 1] = pk_bf16(p2 - bflo(u23), p3 - bfhi(u23));
            }
        }

        // ---- PV mma (3-term), one pass over V rows ----
        #pragma unroll
        for (int ont = 0; ont < 8; ont++) {
            const int d  = ont * 8 + grp;
            const int x7 = d & 7;
            const uint32_t* vh = VhW + d * 32;
            const uint32_t* vl = VlW + d * 32;
            uint4 h0 = *(const uint4*)&vh[(u0 ^ x7) << 2];
            uint4 h1 = *(const uint4*)&vh[(u1 ^ x7) << 2];
            uint4 g0 = *(const uint4*)&vl[(u0 ^ x7) << 2];
            uint4 g1 = *(const uint4*)&vl[(u1 ^ x7) << 2];
            mma_bf16(o[ont], ph[0], h0.x, h0.y);
            mma_bf16(o[ont], ph[0], g0.x, g0.y);
            mma_bf16(o[ont], pl[0], h0.x, h0.y);
            mma_bf16(o[ont], ph[1], h0.z, h0.w);
            mma_bf16(o[ont], ph[1], g0.z, g0.w);
            mma_bf16(o[ont], pl[1], h0.z, h0.w);
            mma_bf16(o[ont], ph[2], h1.x, h1.y);
            mma_bf16(o[ont], ph[2], g1.x, g1.y);
            mma_bf16(o[ont], pl[2], h1.x, h1.y);
            mma_bf16(o[ont], ph[3], h1.z, h1.w);
            mma_bf16(o[ont], ph[3], g1.z, g1.w);
            mma_bf16(o[ont], pl[3], h1.z, h1.w);
        }
        #pragma unroll
        for (int off = 1; off <= 2; off <<= 1) {
            rs0 += __shfl_xor_sync(0xffffffffu, rs0, off);
            rs1 += __shfl_xor_sync(0xffffffffu, rs1, off);
        }
        l0 = l0 * a0 + rs0;
        l1 = l1 * a1 + rs1;
    }

    // ---- epilogue: tf32-rounded store in FRAG-A layout (proj GEMM input) ----
    const float inv0 = 1.0f / l0;
    const float inv1 = 1.0f / l1;
    #pragma unroll
    for (int ont = 0; ont < 8; ont++) {
        #pragma unroll
        for (int c = 0; c < 4; c++) {
            int col = h * HDIM + ont * 8 + 2 * qid + (c & 1);
            int m   = b * LSEQ + i0 + ((c >> 1) << 3);
            float val = (c < 2) ? o[ont][c] * inv0 : o[ont][c] * inv1;
            int blk = (m >> 4) * (DMOD >> 3) + (col >> 3);
            int inner = ((m & 7) * 4 + (col & 3)) * 4
                      + ((col >> 2) & 1) * 2 + ((m >> 3) & 1);
            y[(size_t)blk * 128 + inner] = __uint_as_float(f2tf32(val));
        }
    }
}

// ===========================================================================
// Launch
// ===========================================================================
extern "C" void kernel_launch(void* const* d_in, const int* in_sizes, int n_in,
                              void* d_out, int out_size)
{
    (void)in_sizes; (void)n_in; (void)out_size;
    const float* x     = (const float*)d_in[0];
    const float* Wqkv  = (const float*)d_in[1];
    const float* bqkv  = (const float*)d_in[2];
    const float* Wproj = (const float*)d_in[3];
    const float* bproj = (const float*)d_in[4];
    float* out = (float*)d_out;

    float *qkvp, *yp, *xr, *wqkvr, *wprojr;
    uint32_t *kwp, *vwp;
    cudaGetSymbolAddress((void**)&qkvp, g_qkv);
    cudaGetSymbolAddress((void**)&yp, g_y);
    cudaGetSymbolAddress((void**)&xr, g_xr);
    cudaGetSymbolAddress((void**)&wqkvr, g_wqkvr);
    cudaGetSymbolAddress((void**)&wprojr, g_wprojr);
    cudaGetSymbolAddress((void**)&kwp, g_kw);
    cudaGetSymbolAddress((void**)&vwp, g_vw);

    static bool attr_set = false;
    if (!attr_set) {
        cudaFuncSetAttribute(gemm_tc, cudaFuncAttributeMaxDynamicSharedMemorySize,
                             GEMM_SMEM);
        cudaFuncSetAttribute(attn_mma, cudaFuncAttributeMaxDynamicSharedMemorySize,
                             ATTN_SMEM);
        attr_set = true;
    }

    // Pre-passes: round + relayout into fragment-major operand buffers
    {
        int nx = MROWS * DMOD;
        int nq = DMOD * NQKV;
        int np = DMOD * DMOD;
        xfrag_kernel<<<(nx + 255) / 256, 256>>>(x, xr, MROWS, DMOD);
        wfrag_kernel<<<(nq + 255) / 256, 256>>>(Wqkv, wqkvr, DMOD, NQKV);
        wfrag_kernel<<<(np + 255) / 256, 256>>>(Wproj, wprojr, DMOD, DMOD);
    }

    // QKV projection
    gemm_tc<<<dim3(NQKV / 128, MROWS / 128), 256, GEMM_SMEM>>>(
        xr, wqkvr, bqkv, qkvp, MROWS, NQKV, DMOD);
    // K/V -> frag-unit bf16 hi/lo tiles
    kvconv_kernel<<<dim3(32, 64), 128>>>(qkvp, kwp, vwp);
    // Causal flash attention (epilogue emits frag-A y)
    attn_mma<<<dim3(LSEQ / 64, BSZ * NHEAD), 128, ATTN_SMEM>>>(qkvp, kwp, vwp, yp);
    // Output projection
    gemm_tc<<<dim3(DMOD / 128, MROWS / 128), 256, GEMM_SMEM>>>(
        yp, wprojr, bproj, out, MROWS, DMOD, DMOD);
}